// round 7
// baseline (speedup 1.0000x reference)
#include <cuda_runtime.h>
#include <math.h>

#define N_IMG 2
#define C_IN 48
#define H 192
#define W 192
#define HW (H*W)          // 36864
#define NHW (N_IMG*HW)    // 73728
#define DIM 128
#define PE_DIM 48
#define SCALE 0.25f
#define TWO_PI 6.283185307179586f
#define EPS_F 1e-6f

// scratch
__device__ float g_kv[(size_t)NHW * 256];   // [p][256]: 0:128 = k, 128:256 = v
__device__ float g_q [(size_t)NHW * 128];   // [p][128]
__device__ float g_pe[24 * NHW];            // [k][p] channel-major PE of frac_x
__device__ int   g_x0[NHW];
__device__ float g_pbk[4 * DIM];            // pb @ k_w  (no bias)
__device__ float g_pbv[4 * DIM];            // pb @ v_w

__constant__ float c_inv_dt[12] = {
    1.0f, 0.46415888336127786f, 0.21544346900318834f, 0.1f,
    0.046415888336127774f, 0.021544346900318832f, 0.01f,
    0.0046415888336127786f, 0.0021544346900318834f, 0.001f,
    0.00046415888336127786f, 0.00021544346900318834f
};

typedef unsigned long long ull;
__device__ __forceinline__ ull pk2(float x, float y) {
    ull r; asm("mov.b64 %0,{%1,%2};" : "=l"(r) : "f"(x), "f"(y)); return r;
}
__device__ __forceinline__ ull ffma2(ull a, ull b, ull c) {
    ull d; asm("fma.rn.f32x2 %0,%1,%2,%3;" : "=l"(d) : "l"(a), "l"(b), "l"(c)); return d;
}
__device__ __forceinline__ float2 upk(ull a) {
    float2 r; asm("mov.b64 {%0,%1},%2;" : "=f"(r.x), "=f"(r.y) : "l"(a)); return r;
}

// ---------------------------------------------------------------------------
// K0: window-position-bias projected through k_w / v_w (NO bias; GEMM adds it)
// one block per window tap j
// ---------------------------------------------------------------------------
__global__ void pb_kernel(const float* __restrict__ kw, const float* __restrict__ vw) {
    int o = threadIdx.x;  // 0..127
    int j = blockIdx.x;   // 0..3
    float dy = (float)(j >> 1);
    float dx = (float)(j & 1);
    float yv_ = dy / (1.0f + EPS_F) * TWO_PI;
    float xv_ = dx / (1.0f + EPS_F) * TWO_PI;
    float acck = 0.0f, accv = 0.0f;
    #pragma unroll
    for (int m = 0; m < 12; m++) {
        float sy, cy, sx, cx;
        __sincosf(yv_ * c_inv_dt[m], &sy, &cy);
        __sincosf(xv_ * c_inv_dt[m], &sx, &cx);
        acck += sy * kw[(2*m)*DIM + o]    + cy * kw[(2*m+1)*DIM + o]
              + sx * kw[(24+2*m)*DIM + o] + cx * kw[(25+2*m)*DIM + o];
        accv += sy * vw[(2*m)*DIM + o]    + cy * vw[(2*m+1)*DIM + o]
              + sx * vw[(24+2*m)*DIM + o] + cx * vw[(25+2*m)*DIM + o];
    }
    g_pbk[j*DIM + o] = acck;
    g_pbv[j*DIM + o] = accv;
}

// ---------------------------------------------------------------------------
// K1: 3x3 conv (96ch -> 1) => offset; also writes floor index + PE(frac_x)
// ---------------------------------------------------------------------------
__global__ void conv_kernel(const float* __restrict__ y, const float* __restrict__ x,
                            const float* __restrict__ cw, const float* __restrict__ cb) {
    __shared__ float sw[96 * 9];
    int tid = threadIdx.y * 32 + threadIdx.x;
    for (int i = tid; i < 96 * 9; i += 256) sw[i] = cw[i];
    __syncthreads();

    int w0 = blockIdx.x * 32 + threadIdx.x;
    int h0 = blockIdx.y * 8 + threadIdx.y;
    int n  = blockIdx.z;

    const float* ybase = y + (size_t)n * C_IN * HW;
    const float* xbase = x + (size_t)n * C_IN * HW;

    float acc = cb[0];
    for (int ic = 0; ic < 96; ic++) {
        const float* src = (ic < 48) ? (ybase + ic * HW) : (xbase + (ic - 48) * HW);
        const float* wr = &sw[ic * 9];
        #pragma unroll
        for (int kh = 0; kh < 3; kh++) {
            int hh = h0 + kh - 1;
            if (hh < 0 || hh >= H) continue;
            const float* row = src + hh * W;
            #pragma unroll
            for (int kx = 0; kx < 3; kx++) {
                int ww = w0 + kx - 1;
                if (ww < 0 || ww >= W) continue;
                acc += row[ww] * wr[kh * 3 + kx];
            }
        }
    }
    float offv = acc * (2.0f / (float)W);
    float gx = (float)w0 + offv;
    float fl = floorf(gx);
    int p = n * HW + h0 * W + w0;
    g_x0[p] = (int)fl;
    float xe = (gx - fl) * (TWO_PI / (2.0f + EPS_F));
    #pragma unroll
    for (int m = 0; m < 12; m++) {
        float s, c;
        __sincosf(xe * c_inv_dt[m], &s, &c);
        g_pe[(2*m)   * NHW + p] = s;
        g_pe[(2*m+1) * NHW + p] = c;
    }
}

// ---------------------------------------------------------------------------
// K2: fused tiled GEMM, BM=128 BN=128 K=48, 256 threads, 8x8 microtile, f32x2.
// grid.y: 0 = k (g_kv cols 0:128), 1 = v (g_kv cols 128:256), 2 = q (g_q).
// B tile stored permuted so each lane's 8 columns are two contiguous 16B
// chunks at [tx*4] and [64+tx*4] (conflict-free LDS.128).
// ---------------------------------------------------------------------------
__global__ void __launch_bounds__(256) gemm_kernel(
        const float* __restrict__ y, const float* __restrict__ x,
        const float* __restrict__ qw, const float* __restrict__ qb,
        const float* __restrict__ kw, const float* __restrict__ kb,
        const float* __restrict__ vw, const float* __restrict__ vb) {
    __shared__ float As[48][128];   // 24 KB
    __shared__ float Bs[48][128];   // 24 KB

    int tid = threadIdx.x;
    int bx = blockIdx.x, by = blockIdx.y;
    int p0 = bx * 128;
    int n = p0 / HW;
    int hw0 = p0 - n * HW;
    bool isQ = (by == 2);

    // ---- A tile [48][128] ----
    {
        int i = tid & 127;
        int chalf = tid >> 7;
        if (!isQ) {
            const float* yb = y + (size_t)n * C_IN * HW + hw0 + i;
            #pragma unroll
            for (int c = chalf; c < 48; c += 2) As[c][i] = yb[(size_t)c * HW];
        } else {
            const float* xb = x + (size_t)n * C_IN * HW + hw0 + i;
            int p = p0 + i;
            #pragma unroll
            for (int c = chalf; c < 48; c += 2) {
                float v = xb[(size_t)c * HW];
                if (c < 24) v += (float)(c & 1);
                else        v += g_pe[(c - 24) * NHW + p];
                As[c][i] = v;
            }
        }
    }

    // ---- B tile [48][128], permuted ----
    const float* Wm; const float* bias;
    if (by == 0)      { Wm = kw; bias = kb; }
    else if (by == 1) { Wm = vw; bias = vb; }
    else              { Wm = qw; bias = qb; }
    #pragma unroll
    for (int kk = 0; kk < 24; kk++) {
        int idx = tid + kk * 256;
        int c = idx >> 7, o = idx & 127;
        int perm = ((o & 4) << 4) | ((o >> 3) << 2) | (o & 3);
        Bs[c][perm] = Wm[c * DIM + o];
    }
    __syncthreads();

    int tx = tid & 15, ty = tid >> 4;
    int colb = tx * 8;        // logical output-column base
    int pr0 = ty * 8;         // row base

    ull acc[4][8];
    {
        float4 bb0 = *(const float4*)&bias[colb];
        float4 bb1 = *(const float4*)&bias[colb + 4];
        float bv[8] = {bb0.x, bb0.y, bb0.z, bb0.w, bb1.x, bb1.y, bb1.z, bb1.w};
        #pragma unroll
        for (int m2 = 0; m2 < 4; m2++)
            #pragma unroll
            for (int nn = 0; nn < 8; nn++)
                acc[m2][nn] = pk2(bv[nn], bv[nn]);
    }

    #pragma unroll 4
    for (int c = 0; c < 48; c++) {
        ull a0 = *(const ull*)&As[c][pr0];
        ull a1 = *(const ull*)&As[c][pr0 + 2];
        ull a2 = *(const ull*)&As[c][pr0 + 4];
        ull a3 = *(const ull*)&As[c][pr0 + 6];
        float4 f0 = *(const float4*)&Bs[c][tx * 4];
        float4 f1 = *(const float4*)&Bs[c][64 + tx * 4];
        ull b[8];
        b[0] = pk2(f0.x, f0.x); b[1] = pk2(f0.y, f0.y);
        b[2] = pk2(f0.z, f0.z); b[3] = pk2(f0.w, f0.w);
        b[4] = pk2(f1.x, f1.x); b[5] = pk2(f1.y, f1.y);
        b[6] = pk2(f1.z, f1.z); b[7] = pk2(f1.w, f1.w);
        #pragma unroll
        for (int nn = 0; nn < 8; nn++) {
            acc[0][nn] = ffma2(a0, b[nn], acc[0][nn]);
            acc[1][nn] = ffma2(a1, b[nn], acc[1][nn]);
            acc[2][nn] = ffma2(a2, b[nn], acc[2][nn]);
            acc[3][nn] = ffma2(a3, b[nn], acc[3][nn]);
        }
    }

    float* C; int ld, oc;
    if (isQ) { C = g_q + (size_t)p0 * 128; ld = 128; oc = colb; }
    else     { C = g_kv + (size_t)p0 * 256; ld = 256; oc = colb + (by == 1 ? 128 : 0); }
    #pragma unroll
    for (int m2 = 0; m2 < 4; m2++) {
        float2 cc[8];
        #pragma unroll
        for (int nn = 0; nn < 8; nn++) cc[nn] = upk(acc[m2][nn]);
        int pr = pr0 + m2 * 2;
        float4 e0 = make_float4(cc[0].x, cc[1].x, cc[2].x, cc[3].x);
        float4 e1 = make_float4(cc[4].x, cc[5].x, cc[6].x, cc[7].x);
        float4 o0 = make_float4(cc[0].y, cc[1].y, cc[2].y, cc[3].y);
        float4 o1 = make_float4(cc[4].y, cc[5].y, cc[6].y, cc[7].y);
        *(float4*)&C[(size_t)pr * ld + oc]           = e0;
        *(float4*)&C[(size_t)pr * ld + oc + 4]       = e1;
        *(float4*)&C[(size_t)(pr + 1) * ld + oc]     = o0;
        *(float4*)&C[(size_t)(pr + 1) * ld + oc + 4] = o1;
    }
}

// ---------------------------------------------------------------------------
// K3: warp-per-pixel attention, lane owns 4 channels (c0 = lane*4).
// head group = 4 lanes; dot reduction = 2 shuffles. All LDGs are float4.
// ---------------------------------------------------------------------------
__global__ void __launch_bounds__(512) attn_kernel(float* __restrict__ out) {
    __shared__ float spbk[4][128];
    __shared__ float spbv[4][128];
    __shared__ float sout[128][17];

    int tid = threadIdx.x;
    spbk[tid >> 7][tid & 127] = g_pbk[tid];
    spbv[tid >> 7][tid & 127] = g_pbv[tid];
    __syncthreads();

    int w = tid >> 5;
    int lane = tid & 31;
    int p = blockIdx.x * 16 + w;
    int n = p / HW;
    int hw = p - n * HW;
    int gh = hw / W;
    int x0 = g_x0[p];

    int lin[4];
    #pragma unroll
    for (int j = 0; j < 4; j++) {
        int iy = min(max(gh + (j >> 1), 0), H - 1);
        int ix = min(max(x0 + (j & 1),  0), W - 1);
        lin[j] = n * HW + iy * W + ix;
    }

    int c0 = lane * 4;  // == head*16 + sub*4
    float4 q4 = *(const float4*)&g_q[(size_t)p * 128 + c0];
    q4.x *= SCALE; q4.y *= SCALE; q4.z *= SCALE; q4.w *= SCALE;

    float s[4];
    float4 v4[4];
    #pragma unroll
    for (int j = 0; j < 4; j++) {
        const float* r = g_kv + (size_t)lin[j] * 256;
        float4 k4 = *(const float4*)&r[c0];
        float4 pk = *(const float4*)&spbk[j][c0];
        float4 vv = *(const float4*)&r[128 + c0];
        float4 pv = *(const float4*)&spbv[j][c0];
        v4[j].x = vv.x + pv.x; v4[j].y = vv.y + pv.y;
        v4[j].z = vv.z + pv.z; v4[j].w = vv.w + pv.w;
        float part = q4.x * (k4.x + pk.x) + q4.y * (k4.y + pk.y)
                   + q4.z * (k4.z + pk.z) + q4.w * (k4.w + pk.w);
        part += __shfl_xor_sync(0xffffffffu, part, 1);
        part += __shfl_xor_sync(0xffffffffu, part, 2);
        s[j] = part;
    }

    float mx = fmaxf(fmaxf(s[0], s[1]), fmaxf(s[2], s[3]));
    float e0 = __expf(s[0] - mx), e1 = __expf(s[1] - mx);
    float e2 = __expf(s[2] - mx), e3 = __expf(s[3] - mx);
    float inv = 1.0f / (e0 + e1 + e2 + e3);
    float a0 = e0 * inv, a1 = e1 * inv, a2 = e2 * inv, a3 = e3 * inv;

    float4 o4;
    o4.x = a0 * v4[0].x + a1 * v4[1].x + a2 * v4[2].x + a3 * v4[3].x;
    o4.y = a0 * v4[0].y + a1 * v4[1].y + a2 * v4[2].y + a3 * v4[3].y;
    o4.z = a0 * v4[0].z + a1 * v4[1].z + a2 * v4[2].z + a3 * v4[3].z;
    o4.w = a0 * v4[0].w + a1 * v4[1].w + a2 * v4[2].w + a3 * v4[3].w;

    sout[c0 + 0][w] = o4.x;
    sout[c0 + 1][w] = o4.y;
    sout[c0 + 2][w] = o4.z;
    sout[c0 + 3][w] = o4.w;
    __syncthreads();

    // coalesced NCHW write: block covers 16 consecutive hw in one image row
    int p0 = blockIdx.x * 16;
    int n0 = p0 / HW;
    int hw0 = p0 - n0 * HW;
    int ch = tid >> 2;
    int px = (tid & 3) * 4;
    float4 v = make_float4(sout[ch][px], sout[ch][px + 1], sout[ch][px + 2], sout[ch][px + 3]);
    *(float4*)&out[(size_t)n0 * DIM * HW + (size_t)ch * HW + hw0 + px] = v;
}

// ---------------------------------------------------------------------------
extern "C" void kernel_launch(void* const* d_in, const int* in_sizes, int n_in,
                              void* d_out, int out_size) {
    const float* y      = (const float*)d_in[0];
    const float* x      = (const float*)d_in[1];
    const float* conv_w = (const float*)d_in[2];
    const float* conv_b = (const float*)d_in[3];
    const float* q_w    = (const float*)d_in[4];
    const float* q_b    = (const float*)d_in[5];
    const float* k_w    = (const float*)d_in[6];
    const float* k_b    = (const float*)d_in[7];
    const float* v_w    = (const float*)d_in[8];
    const float* v_b    = (const float*)d_in[9];
    float* out = (float*)d_out;

    pb_kernel<<<4, 128>>>(k_w, v_w);

    dim3 cgrid(W / 32, H / 8, N_IMG);
    dim3 cblk(32, 8);
    conv_kernel<<<cgrid, cblk>>>(y, x, conv_w, conv_b);

    dim3 ggrid(NHW / 128, 3);
    gemm_kernel<<<ggrid, 256>>>(y, x, q_w, q_b, k_w, k_b, v_w, v_b);

    attn_kernel<<<NHW / 16, 512>>>(out);
}

// round 8
// speedup vs baseline: 1.3438x; 1.3438x over previous
#include <cuda_runtime.h>
#include <math.h>

#define N_IMG 2
#define C_IN 48
#define H 192
#define W 192
#define HW (H*W)          // 36864
#define NHW (N_IMG*HW)    // 73728
#define DIM 128
#define PE_DIM 48
#define SCALE 0.25f
#define TWO_PI 6.283185307179586f
#define EPS_F 1e-6f

// scratch
__device__ float g_kv[(size_t)NHW * 256];   // [p][256]: 0:128 = k, 128:256 = v
__device__ float g_q [(size_t)NHW * 128];   // [p][128]
__device__ float g_pe[24 * NHW];            // [k][p] channel-major PE of frac_x
__device__ int   g_x0[NHW];
__device__ float g_pbk[4 * DIM];            // pb @ k_w  (no bias)
__device__ float g_pbv[4 * DIM];            // pb @ v_w

__constant__ float c_inv_dt[12] = {
    1.0f, 0.46415888336127786f, 0.21544346900318834f, 0.1f,
    0.046415888336127774f, 0.021544346900318832f, 0.01f,
    0.0046415888336127786f, 0.0021544346900318834f, 0.001f,
    0.00046415888336127786f, 0.00021544346900318834f
};

typedef unsigned long long ull;
__device__ __forceinline__ ull pk2(float x, float y) {
    ull r; asm("mov.b64 %0,{%1,%2};" : "=l"(r) : "f"(x), "f"(y)); return r;
}
__device__ __forceinline__ ull ffma2(ull a, ull b, ull c) {
    ull d; asm("fma.rn.f32x2 %0,%1,%2,%3;" : "=l"(d) : "l"(a), "l"(b), "l"(c)); return d;
}
__device__ __forceinline__ float2 upk(ull a) {
    float2 r; asm("mov.b64 {%0,%1},%2;" : "=f"(r.x), "=f"(r.y) : "l"(a)); return r;
}

// ---------------------------------------------------------------------------
// K0: window-position-bias projected through k_w / v_w (NO bias; GEMM adds it)
// ---------------------------------------------------------------------------
__global__ void pb_kernel(const float* __restrict__ kw, const float* __restrict__ vw) {
    int o = threadIdx.x;  // 0..127
    int j = blockIdx.x;   // 0..3
    float dy = (float)(j >> 1);
    float dx = (float)(j & 1);
    float yv_ = dy / (1.0f + EPS_F) * TWO_PI;
    float xv_ = dx / (1.0f + EPS_F) * TWO_PI;
    float acck = 0.0f, accv = 0.0f;
    #pragma unroll
    for (int m = 0; m < 12; m++) {
        float sy, cy, sx, cx;
        __sincosf(yv_ * c_inv_dt[m], &sy, &cy);
        __sincosf(xv_ * c_inv_dt[m], &sx, &cx);
        acck += sy * kw[(2*m)*DIM + o]    + cy * kw[(2*m+1)*DIM + o]
              + sx * kw[(24+2*m)*DIM + o] + cx * kw[(25+2*m)*DIM + o];
        accv += sy * vw[(2*m)*DIM + o]    + cy * vw[(2*m+1)*DIM + o]
              + sx * vw[(24+2*m)*DIM + o] + cx * vw[(25+2*m)*DIM + o];
    }
    g_pbk[j*DIM + o] = acck;
    g_pbv[j*DIM + o] = accv;
}

// ---------------------------------------------------------------------------
// K1: 3x3 conv (96ch -> 1) => offset; writes floor index + PE(frac_x)
// ---------------------------------------------------------------------------
__global__ void conv_kernel(const float* __restrict__ y, const float* __restrict__ x,
                            const float* __restrict__ cw, const float* __restrict__ cb) {
    __shared__ float sw[96 * 9];
    int tid = threadIdx.y * 32 + threadIdx.x;
    for (int i = tid; i < 96 * 9; i += 256) sw[i] = cw[i];
    __syncthreads();

    int w0 = blockIdx.x * 32 + threadIdx.x;
    int h0 = blockIdx.y * 8 + threadIdx.y;
    int n  = blockIdx.z;

    const float* ybase = y + (size_t)n * C_IN * HW;
    const float* xbase = x + (size_t)n * C_IN * HW;

    float acc = cb[0];
    for (int ic = 0; ic < 96; ic++) {
        const float* src = (ic < 48) ? (ybase + ic * HW) : (xbase + (ic - 48) * HW);
        const float* wr = &sw[ic * 9];
        #pragma unroll
        for (int kh = 0; kh < 3; kh++) {
            int hh = h0 + kh - 1;
            if (hh < 0 || hh >= H) continue;
            const float* row = src + hh * W;
            #pragma unroll
            for (int kx = 0; kx < 3; kx++) {
                int ww = w0 + kx - 1;
                if (ww < 0 || ww >= W) continue;
                acc += row[ww] * wr[kh * 3 + kx];
            }
        }
    }
    float offv = acc * (2.0f / (float)W);
    float gx = (float)w0 + offv;
    float fl = floorf(gx);
    int p = n * HW + h0 * W + w0;
    g_x0[p] = (int)fl;
    float xe = (gx - fl) * (TWO_PI / (2.0f + EPS_F));
    #pragma unroll
    for (int m = 0; m < 12; m++) {
        float s, c;
        __sincosf(xe * c_inv_dt[m], &s, &c);
        g_pe[(2*m)   * NHW + p] = s;
        g_pe[(2*m+1) * NHW + p] = c;
    }
}

// ---------------------------------------------------------------------------
// K2: fused tiled GEMM — ONE block per 128-pixel tile computes all 384 output
// columns (k 0:128, v 0:128 from y; q 0:128 from x). A_y/A_x loaded to smem
// once; 6 column passes of 64 cols stream weights via double-buffered Bs.
// 256 threads, 8x4 microtile, packed f32x2 FMA.
// ---------------------------------------------------------------------------
__global__ void __launch_bounds__(256) gemm_kernel(
        const float* __restrict__ y, const float* __restrict__ x,
        const float* __restrict__ qw, const float* __restrict__ qb,
        const float* __restrict__ kw, const float* __restrict__ kb,
        const float* __restrict__ vw, const float* __restrict__ vb) {
    __shared__ float Ay[48][128];     // 24 KB
    __shared__ float Ax[48][128];     // 24 KB
    __shared__ float Bs[2][48][64];   // 24 KB

    int tid = threadIdx.x;
    int p0 = blockIdx.x * 128;
    int n = p0 / HW;
    int hw0 = p0 - n * HW;

    // ---- load A tiles once ----
    {
        int i = tid & 127;
        int chalf = tid >> 7;
        const float* yb = y + (size_t)n * C_IN * HW + hw0 + i;
        const float* xb = x + (size_t)n * C_IN * HW + hw0 + i;
        int p = p0 + i;
        #pragma unroll
        for (int c = chalf; c < 48; c += 2) {
            Ay[c][i] = yb[(size_t)c * HW];
            float v = xb[(size_t)c * HW];
            if (c < 24) v += (float)(c & 1);
            else        v += g_pe[(c - 24) * NHW + p];
            Ax[c][i] = v;
        }
    }

    // ---- preload B tile for pass 0 (kw cols 0:64) ----
    {
        int c = tid >> 6, o = tid & 63;
        #pragma unroll
        for (int kk = 0; kk < 12; kk++)
            Bs[0][c + kk * 4][o] = kw[(c + kk * 4) * DIM + o];
    }
    __syncthreads();

    int tx = tid & 15, ty = tid >> 4;
    int otx = tx * 4, pr0 = ty * 8;

    #pragma unroll 1
    for (int pass = 0; pass < 6; pass++) {
        int buf = pass & 1;
        const float (*A)[128] = (pass < 4) ? Ay : Ax;
        const float* bias = (pass < 2) ? kb : (pass < 4) ? vb : qb;
        int o0 = (pass & 1) * 64;

        // prefetch next pass's B tile into registers (overlaps compute)
        float nb[12];
        int nc = tid >> 6, no = tid & 63;
        if (pass < 5) {
            int np = pass + 1;
            const float* Wn = (np < 2) ? kw : (np < 4) ? vw : qw;
            int no0 = (np & 1) * 64;
            #pragma unroll
            for (int kk = 0; kk < 12; kk++)
                nb[kk] = Wn[(nc + kk * 4) * DIM + no0 + no];
        }

        // ---- compute 128x64 ----
        ull acc[4][4];
        {
            float4 bb = *(const float4*)&bias[o0 + otx];
            #pragma unroll
            for (int pp = 0; pp < 4; pp++) {
                acc[pp][0] = pk2(bb.x, bb.x);
                acc[pp][1] = pk2(bb.y, bb.y);
                acc[pp][2] = pk2(bb.z, bb.z);
                acc[pp][3] = pk2(bb.w, bb.w);
            }
        }
        #pragma unroll 8
        for (int c = 0; c < 48; c++) {
            ull a0 = *(const ull*)&A[c][pr0];
            ull a1 = *(const ull*)&A[c][pr0 + 2];
            ull a2 = *(const ull*)&A[c][pr0 + 4];
            ull a3 = *(const ull*)&A[c][pr0 + 6];
            float4 b4 = *(const float4*)&Bs[buf][c][otx];
            ull b0 = pk2(b4.x, b4.x), b1 = pk2(b4.y, b4.y);
            ull b2 = pk2(b4.z, b4.z), b3 = pk2(b4.w, b4.w);
            acc[0][0] = ffma2(a0, b0, acc[0][0]); acc[0][1] = ffma2(a0, b1, acc[0][1]);
            acc[0][2] = ffma2(a0, b2, acc[0][2]); acc[0][3] = ffma2(a0, b3, acc[0][3]);
            acc[1][0] = ffma2(a1, b0, acc[1][0]); acc[1][1] = ffma2(a1, b1, acc[1][1]);
            acc[1][2] = ffma2(a1, b2, acc[1][2]); acc[1][3] = ffma2(a1, b3, acc[1][3]);
            acc[2][0] = ffma2(a2, b0, acc[2][0]); acc[2][1] = ffma2(a2, b1, acc[2][1]);
            acc[2][2] = ffma2(a2, b2, acc[2][2]); acc[2][3] = ffma2(a2, b3, acc[2][3]);
            acc[3][0] = ffma2(a3, b0, acc[3][0]); acc[3][1] = ffma2(a3, b1, acc[3][1]);
            acc[3][2] = ffma2(a3, b2, acc[3][2]); acc[3][3] = ffma2(a3, b3, acc[3][3]);
        }

        // ---- store this pass ----
        float* C; int ld, oc;
        if (pass < 2)      { C = g_kv + (size_t)p0 * 256; ld = 256; oc = pass * 64 + otx; }
        else if (pass < 4) { C = g_kv + (size_t)p0 * 256; ld = 256; oc = 128 + (pass - 2) * 64 + otx; }
        else               { C = g_q  + (size_t)p0 * 128; ld = 128; oc = (pass - 4) * 64 + otx; }
        #pragma unroll
        for (int pp = 0; pp < 4; pp++) {
            float2 c0 = upk(acc[pp][0]), c1 = upk(acc[pp][1]);
            float2 c2 = upk(acc[pp][2]), c3 = upk(acc[pp][3]);
            int pr = pr0 + 2 * pp;
            *(float4*)&C[(size_t)pr * ld + oc]       = make_float4(c0.x, c1.x, c2.x, c3.x);
            *(float4*)&C[(size_t)(pr + 1) * ld + oc] = make_float4(c0.y, c1.y, c2.y, c3.y);
        }

        // ---- publish next B tile ----
        if (pass < 5) {
            #pragma unroll
            for (int kk = 0; kk < 12; kk++)
                Bs[buf ^ 1][nc + kk * 4][no] = nb[kk];
        }
        __syncthreads();
    }
}

// ---------------------------------------------------------------------------
// K3: warp-per-pixel attention (R5 version). 512 threads = 16 pixels/block.
// lane <-> channel (c = lane + 32*i), 16-lane shuffle reduction per head.
// ---------------------------------------------------------------------------
__global__ void __launch_bounds__(512) attn_kernel(float* __restrict__ out) {
    __shared__ float spbk[4][128];
    __shared__ float spbv[4][128];
    __shared__ float sout[128][17];

    int tid = threadIdx.x;
    spbk[tid >> 7][tid & 127] = g_pbk[tid];
    spbv[tid >> 7][tid & 127] = g_pbv[tid];
    __syncthreads();

    int w  = tid >> 5;
    int lane = tid & 31;
    int p = blockIdx.x * 16 + w;
    int n = p / HW;
    int hw = p - n * HW;
    int gh = hw / W;
    int x0 = g_x0[p];

    int lin[4];
    #pragma unroll
    for (int j = 0; j < 4; j++) {
        int iy = min(max(gh + (j >> 1), 0), H - 1);
        int ix = min(max(x0 + (j & 1),  0), W - 1);
        lin[j] = n * HW + iy * W + ix;
    }

    const float* qrow = g_q + (size_t)p * 128;

    #pragma unroll
    for (int i = 0; i < 4; i++) {
        int c = lane + 32 * i;
        float qv = qrow[c] * SCALE;
        float kj[4], vj[4], s[4];
        #pragma unroll
        for (int j = 0; j < 4; j++) {
            const float* r = g_kv + (size_t)lin[j] * 256;
            kj[j] = r[c]       + spbk[j][c];
            vj[j] = r[128 + c] + spbv[j][c];
            float part = qv * kj[j];
            part += __shfl_xor_sync(0xffffffffu, part, 8);
            part += __shfl_xor_sync(0xffffffffu, part, 4);
            part += __shfl_xor_sync(0xffffffffu, part, 2);
            part += __shfl_xor_sync(0xffffffffu, part, 1);
            s[j] = part;
        }
        float mx = fmaxf(fmaxf(s[0], s[1]), fmaxf(s[2], s[3]));
        float e0 = __expf(s[0] - mx), e1 = __expf(s[1] - mx);
        float e2 = __expf(s[2] - mx), e3 = __expf(s[3] - mx);
        float inv = 1.0f / (e0 + e1 + e2 + e3);
        float oo = (e0 * vj[0] + e1 * vj[1] + e2 * vj[2] + e3 * vj[3]) * inv;
        sout[c][w] = oo;
    }
    __syncthreads();

    int p0 = blockIdx.x * 16;
    int n0 = p0 / HW;
    int hw0 = p0 - n0 * HW;
    int ch = tid >> 2;
    int px = (tid & 3) * 4;
    float4 v = make_float4(sout[ch][px], sout[ch][px + 1], sout[ch][px + 2], sout[ch][px + 3]);
    *(float4*)&out[(size_t)n0 * DIM * HW + (size_t)ch * HW + hw0 + px] = v;
}

// ---------------------------------------------------------------------------
extern "C" void kernel_launch(void* const* d_in, const int* in_sizes, int n_in,
                              void* d_out, int out_size) {
    const float* y      = (const float*)d_in[0];
    const float* x      = (const float*)d_in[1];
    const float* conv_w = (const float*)d_in[2];
    const float* conv_b = (const float*)d_in[3];
    const float* q_w    = (const float*)d_in[4];
    const float* q_b    = (const float*)d_in[5];
    const float* k_w    = (const float*)d_in[6];
    const float* k_b    = (const float*)d_in[7];
    const float* v_w    = (const float*)d_in[8];
    const float* v_b    = (const float*)d_in[9];
    float* out = (float*)d_out;

    pb_kernel<<<4, 128>>>(k_w, v_w);

    dim3 cgrid(W / 32, H / 8, N_IMG);
    dim3 cblk(32, 8);
    conv_kernel<<<cgrid, cblk>>>(y, x, conv_w, conv_b);

    gemm_kernel<<<NHW / 128, 256>>>(y, x, q_w, q_b, k_w, k_b, v_w, v_b);

    attn_kernel<<<NHW / 16, 512>>>(out);
}

// round 9
// speedup vs baseline: 1.4892x; 1.1082x over previous
#include <cuda_runtime.h>
#include <cuda_fp16.h>
#include <math.h>

#define N_IMG 2
#define C_IN 48
#define H 192
#define W 192
#define HW (H*W)          // 36864
#define NHW (N_IMG*HW)    // 73728
#define DIM 128
#define PE_DIM 48
#define SCALE 0.25f
#define TWO_PI 6.283185307179586f
#define EPS_F 1e-6f

// scratch
__device__ __half g_kv[(size_t)NHW * 256];  // [p][256]: 0:128 = k, 128:256 = v (fp16)
__device__ __half g_q [(size_t)NHW * 128];  // [p][128] (fp16, pre-scaled by SCALE)
__device__ float  g_pe[24 * NHW];           // [k][p] channel-major PE of frac_x
__device__ int    g_x0[NHW];
__device__ float  g_pbk[4 * DIM];           // pb @ k_w  (no bias)
__device__ float  g_pbv[4 * DIM];           // pb @ v_w

__constant__ float c_inv_dt[12] = {
    1.0f, 0.46415888336127786f, 0.21544346900318834f, 0.1f,
    0.046415888336127774f, 0.021544346900318832f, 0.01f,
    0.0046415888336127786f, 0.0021544346900318834f, 0.001f,
    0.00046415888336127786f, 0.00021544346900318834f
};

typedef unsigned long long ull;
__device__ __forceinline__ ull pk2(float x, float y) {
    ull r; asm("mov.b64 %0,{%1,%2};" : "=l"(r) : "f"(x), "f"(y)); return r;
}
__device__ __forceinline__ ull ffma2(ull a, ull b, ull c) {
    ull d; asm("fma.rn.f32x2 %0,%1,%2,%3;" : "=l"(d) : "l"(a), "l"(b), "l"(c)); return d;
}
__device__ __forceinline__ float2 upk(ull a) {
    float2 r; asm("mov.b64 {%0,%1},%2;" : "=f"(r.x), "=f"(r.y) : "l"(a)); return r;
}

// ---------------------------------------------------------------------------
// K0: window-position-bias projected through k_w / v_w (NO bias; GEMM adds it)
// ---------------------------------------------------------------------------
__global__ void pb_kernel(const float* __restrict__ kw, const float* __restrict__ vw) {
    int o = threadIdx.x;  // 0..127
    int j = blockIdx.x;   // 0..3
    float dy = (float)(j >> 1);
    float dx = (float)(j & 1);
    float yv_ = dy / (1.0f + EPS_F) * TWO_PI;
    float xv_ = dx / (1.0f + EPS_F) * TWO_PI;
    float acck = 0.0f, accv = 0.0f;
    #pragma unroll
    for (int m = 0; m < 12; m++) {
        float sy, cy, sx, cx;
        __sincosf(yv_ * c_inv_dt[m], &sy, &cy);
        __sincosf(xv_ * c_inv_dt[m], &sx, &cx);
        acck += sy * kw[(2*m)*DIM + o]    + cy * kw[(2*m+1)*DIM + o]
              + sx * kw[(24+2*m)*DIM + o] + cx * kw[(25+2*m)*DIM + o];
        accv += sy * vw[(2*m)*DIM + o]    + cy * vw[(2*m+1)*DIM + o]
              + sx * vw[(24+2*m)*DIM + o] + cx * vw[(25+2*m)*DIM + o];
    }
    g_pbk[j*DIM + o] = acck;
    g_pbv[j*DIM + o] = accv;
}

// ---------------------------------------------------------------------------
// K1: 3x3 conv (96ch -> 1) => offset; writes floor index + PE(frac_x)
// ---------------------------------------------------------------------------
__global__ void conv_kernel(const float* __restrict__ y, const float* __restrict__ x,
                            const float* __restrict__ cw, const float* __restrict__ cb) {
    __shared__ float sw[96 * 9];
    int tid = threadIdx.y * 32 + threadIdx.x;
    for (int i = tid; i < 96 * 9; i += 256) sw[i] = cw[i];
    __syncthreads();

    int w0 = blockIdx.x * 32 + threadIdx.x;
    int h0 = blockIdx.y * 8 + threadIdx.y;
    int n  = blockIdx.z;

    const float* ybase = y + (size_t)n * C_IN * HW;
    const float* xbase = x + (size_t)n * C_IN * HW;

    float acc = cb[0];
    for (int ic = 0; ic < 96; ic++) {
        const float* src = (ic < 48) ? (ybase + ic * HW) : (xbase + (ic - 48) * HW);
        const float* wr = &sw[ic * 9];
        #pragma unroll
        for (int kh = 0; kh < 3; kh++) {
            int hh = h0 + kh - 1;
            if (hh < 0 || hh >= H) continue;
            const float* row = src + hh * W;
            #pragma unroll
            for (int kx = 0; kx < 3; kx++) {
                int ww = w0 + kx - 1;
                if (ww < 0 || ww >= W) continue;
                acc += row[ww] * wr[kh * 3 + kx];
            }
        }
    }
    float offv = acc * (2.0f / (float)W);
    float gx = (float)w0 + offv;
    float fl = floorf(gx);
    int p = n * HW + h0 * W + w0;
    g_x0[p] = (int)fl;
    float xe = (gx - fl) * (TWO_PI / (2.0f + EPS_F));
    #pragma unroll
    for (int m = 0; m < 12; m++) {
        float s, c;
        __sincosf(xe * c_inv_dt[m], &s, &c);
        g_pe[(2*m)   * NHW + p] = s;
        g_pe[(2*m+1) * NHW + p] = c;
    }
}

// ---------------------------------------------------------------------------
// K2: fused tiled GEMM — one block per 128-pixel tile computes all 384 output
// columns across 6 passes (k0,k1,v0,v1 from y; q0,q1 from x). fp16 epilogue.
// q passes pre-scale by SCALE. 256 threads, 8x4 microtile, f32x2 FMA.
// ---------------------------------------------------------------------------
__global__ void __launch_bounds__(256) gemm_kernel(
        const float* __restrict__ y, const float* __restrict__ x,
        const float* __restrict__ qw, const float* __restrict__ qb,
        const float* __restrict__ kw, const float* __restrict__ kb,
        const float* __restrict__ vw, const float* __restrict__ vb) {
    __shared__ float Ay[48][128];     // 24 KB
    __shared__ float Ax[48][128];     // 24 KB
    __shared__ float Bs[2][48][64];   // 24 KB

    int tid = threadIdx.x;
    int p0 = blockIdx.x * 128;
    int n = p0 / HW;
    int hw0 = p0 - n * HW;

    // ---- load A tiles once ----
    {
        int i = tid & 127;
        int chalf = tid >> 7;
        const float* yb = y + (size_t)n * C_IN * HW + hw0 + i;
        const float* xb = x + (size_t)n * C_IN * HW + hw0 + i;
        int p = p0 + i;
        #pragma unroll
        for (int c = chalf; c < 48; c += 2) {
            Ay[c][i] = yb[(size_t)c * HW];
            float v = xb[(size_t)c * HW];
            if (c < 24) v += (float)(c & 1);
            else        v += g_pe[(c - 24) * NHW + p];
            Ax[c][i] = v;
        }
    }

    // ---- preload B tile for pass 0 (kw cols 0:64) ----
    {
        int c = tid >> 6, o = tid & 63;
        #pragma unroll
        for (int kk = 0; kk < 12; kk++)
            Bs[0][c + kk * 4][o] = kw[(c + kk * 4) * DIM + o];
    }
    __syncthreads();

    int tx = tid & 15, ty = tid >> 4;
    int otx = tx * 4, pr0 = ty * 8;

    #pragma unroll 1
    for (int pass = 0; pass < 6; pass++) {
        int buf = pass & 1;
        const float (*A)[128] = (pass < 4) ? Ay : Ax;
        const float* bias = (pass < 2) ? kb : (pass < 4) ? vb : qb;
        int o0 = (pass & 1) * 64;
        bool isQ = (pass >= 4);

        // prefetch next pass's B tile into registers (overlaps compute)
        float nb[12];
        int nc = tid >> 6, no = tid & 63;
        if (pass < 5) {
            int np = pass + 1;
            const float* Wn = (np < 2) ? kw : (np < 4) ? vw : qw;
            int no0 = (np & 1) * 64;
            #pragma unroll
            for (int kk = 0; kk < 12; kk++)
                nb[kk] = Wn[(nc + kk * 4) * DIM + no0 + no];
        }

        // ---- compute 128x64 ----
        ull acc[4][4];
        {
            float4 bb = *(const float4*)&bias[o0 + otx];
            #pragma unroll
            for (int pp = 0; pp < 4; pp++) {
                acc[pp][0] = pk2(bb.x, bb.x);
                acc[pp][1] = pk2(bb.y, bb.y);
                acc[pp][2] = pk2(bb.z, bb.z);
                acc[pp][3] = pk2(bb.w, bb.w);
            }
        }
        #pragma unroll 8
        for (int c = 0; c < 48; c++) {
            ull a0 = *(const ull*)&A[c][pr0];
            ull a1 = *(const ull*)&A[c][pr0 + 2];
            ull a2 = *(const ull*)&A[c][pr0 + 4];
            ull a3 = *(const ull*)&A[c][pr0 + 6];
            float4 b4 = *(const float4*)&Bs[buf][c][otx];
            ull b0 = pk2(b4.x, b4.x), b1 = pk2(b4.y, b4.y);
            ull b2 = pk2(b4.z, b4.z), b3 = pk2(b4.w, b4.w);
            acc[0][0] = ffma2(a0, b0, acc[0][0]); acc[0][1] = ffma2(a0, b1, acc[0][1]);
            acc[0][2] = ffma2(a0, b2, acc[0][2]); acc[0][3] = ffma2(a0, b3, acc[0][3]);
            acc[1][0] = ffma2(a1, b0, acc[1][0]); acc[1][1] = ffma2(a1, b1, acc[1][1]);
            acc[1][2] = ffma2(a1, b2, acc[1][2]); acc[1][3] = ffma2(a1, b3, acc[1][3]);
            acc[2][0] = ffma2(a2, b0, acc[2][0]); acc[2][1] = ffma2(a2, b1, acc[2][1]);
            acc[2][2] = ffma2(a2, b2, acc[2][2]); acc[2][3] = ffma2(a2, b3, acc[2][3]);
            acc[3][0] = ffma2(a3, b0, acc[3][0]); acc[3][1] = ffma2(a3, b1, acc[3][1]);
            acc[3][2] = ffma2(a3, b2, acc[3][2]); acc[3][3] = ffma2(a3, b3, acc[3][3]);
        }

        // ---- store this pass (fp16; q pre-scaled) ----
        __half* C; int ld, oc;
        if (pass < 2)      { C = g_kv + (size_t)p0 * 256; ld = 256; oc = pass * 64 + otx; }
        else if (pass < 4) { C = g_kv + (size_t)p0 * 256; ld = 256; oc = 128 + (pass - 2) * 64 + otx; }
        else               { C = g_q  + (size_t)p0 * 128; ld = 128; oc = (pass - 4) * 64 + otx; }
        float sc = isQ ? SCALE : 1.0f;
        #pragma unroll
        for (int pp = 0; pp < 4; pp++) {
            float2 c0 = upk(acc[pp][0]), c1 = upk(acc[pp][1]);
            float2 c2 = upk(acc[pp][2]), c3 = upk(acc[pp][3]);
            int pr = pr0 + 2 * pp;
            __half2 e0 = __float22half2_rn(make_float2(c0.x * sc, c1.x * sc));
            __half2 e1 = __float22half2_rn(make_float2(c2.x * sc, c3.x * sc));
            __half2 o0h = __float22half2_rn(make_float2(c0.y * sc, c1.y * sc));
            __half2 o1h = __float22half2_rn(make_float2(c2.y * sc, c3.y * sc));
            *(__half2*)&C[(size_t)pr * ld + oc]           = e0;
            *(__half2*)&C[(size_t)pr * ld + oc + 2]       = e1;
            *(__half2*)&C[(size_t)(pr + 1) * ld + oc]     = o0h;
            *(__half2*)&C[(size_t)(pr + 1) * ld + oc + 2] = o1h;
        }

        // ---- publish next B tile ----
        if (pass < 5) {
            #pragma unroll
            for (int kk = 0; kk < 12; kk++)
                Bs[buf ^ 1][nc + kk * 4][no] = nb[kk];
        }
        __syncthreads();
    }
}

// ---------------------------------------------------------------------------
// K3: warp-per-pixel attention, lane owns 4 consecutive channels (c0=lane*4),
// fp16 kv/q loads (LDG.64), fp32 math, 2-shuffle head reduction.
// ---------------------------------------------------------------------------
__global__ void __launch_bounds__(512) attn_kernel(float* __restrict__ out) {
    __shared__ float spbk[4][128];
    __shared__ float spbv[4][128];
    __shared__ float sout[128][17];

    int tid = threadIdx.x;
    spbk[tid >> 7][tid & 127] = g_pbk[tid];
    spbv[tid >> 7][tid & 127] = g_pbv[tid];
    __syncthreads();

    int w = tid >> 5;
    int lane = tid & 31;
    int p = blockIdx.x * 16 + w;
    int n = p / HW;
    int hw = p - n * HW;
    int gh = hw / W;
    int x0 = g_x0[p];

    int lin[4];
    #pragma unroll
    for (int j = 0; j < 4; j++) {
        int iy = min(max(gh + (j >> 1), 0), H - 1);
        int ix = min(max(x0 + (j & 1),  0), W - 1);
        lin[j] = n * HW + iy * W + ix;
    }

    int c0 = lane * 4;  // head = lane>>2

    // q (pre-scaled in gemm)
    float4 q4;
    {
        ull qq = *(const ull*)&g_q[(size_t)p * 128 + c0];
        __half2 h0 = ((const __half2*)&qq)[0];
        __half2 h1 = ((const __half2*)&qq)[1];
        float2 f0 = __half22float2(h0), f1 = __half22float2(h1);
        q4 = make_float4(f0.x, f0.y, f1.x, f1.y);
    }

    float s[4];
    float4 v4[4];
    #pragma unroll
    for (int j = 0; j < 4; j++) {
        const __half* r = g_kv + (size_t)lin[j] * 256;
        ull kk = *(const ull*)&r[c0];
        ull vv = *(const ull*)&r[128 + c0];
        float2 k0 = __half22float2(((const __half2*)&kk)[0]);
        float2 k1 = __half22float2(((const __half2*)&kk)[1]);
        float2 w0 = __half22float2(((const __half2*)&vv)[0]);
        float2 w1 = __half22float2(((const __half2*)&vv)[1]);
        float4 pk = *(const float4*)&spbk[j][c0];
        float4 pv = *(const float4*)&spbv[j][c0];
        v4[j].x = w0.x + pv.x; v4[j].y = w0.y + pv.y;
        v4[j].z = w1.x + pv.z; v4[j].w = w1.y + pv.w;
        float part = q4.x * (k0.x + pk.x) + q4.y * (k0.y + pk.y)
                   + q4.z * (k1.x + pk.z) + q4.w * (k1.y + pk.w);
        part += __shfl_xor_sync(0xffffffffu, part, 1);
        part += __shfl_xor_sync(0xffffffffu, part, 2);
        s[j] = part;
    }

    float mx = fmaxf(fmaxf(s[0], s[1]), fmaxf(s[2], s[3]));
    float e0 = __expf(s[0] - mx), e1 = __expf(s[1] - mx);
    float e2 = __expf(s[2] - mx), e3 = __expf(s[3] - mx);
    float inv = 1.0f / (e0 + e1 + e2 + e3);
    float a0 = e0 * inv, a1 = e1 * inv, a2 = e2 * inv, a3 = e3 * inv;

    sout[c0 + 0][w] = a0 * v4[0].x + a1 * v4[1].x + a2 * v4[2].x + a3 * v4[3].x;
    sout[c0 + 1][w] = a0 * v4[0].y + a1 * v4[1].y + a2 * v4[2].y + a3 * v4[3].y;
    sout[c0 + 2][w] = a0 * v4[0].z + a1 * v4[1].z + a2 * v4[2].z + a3 * v4[3].z;
    sout[c0 + 3][w] = a0 * v4[0].w + a1 * v4[1].w + a2 * v4[2].w + a3 * v4[3].w;
    __syncthreads();

    int p0 = blockIdx.x * 16;
    int n0 = p0 / HW;
    int hw0 = p0 - n0 * HW;
    int ch = tid >> 2;
    int px = (tid & 3) * 4;
    float4 v = make_float4(sout[ch][px], sout[ch][px + 1], sout[ch][px + 2], sout[ch][px + 3]);
    *(float4*)&out[(size_t)n0 * DIM * HW + (size_t)ch * HW + hw0 + px] = v;
}

// ---------------------------------------------------------------------------
extern "C" void kernel_launch(void* const* d_in, const int* in_sizes, int n_in,
                              void* d_out, int out_size) {
    const float* y      = (const float*)d_in[0];
    const float* x      = (const float*)d_in[1];
    const float* conv_w = (const float*)d_in[2];
    const float* conv_b = (const float*)d_in[3];
    const float* q_w    = (const float*)d_in[4];
    const float* q_b    = (const float*)d_in[5];
    const float* k_w    = (const float*)d_in[6];
    const float* k_b    = (const float*)d_in[7];
    const float* v_w    = (const float*)d_in[8];
    const float* v_b    = (const float*)d_in[9];
    float* out = (float*)d_out;

    pb_kernel<<<4, 128>>>(k_w, v_w);

    dim3 cgrid(W / 32, H / 8, N_IMG);
    dim3 cblk(32, 8);
    conv_kernel<<<cgrid, cblk>>>(y, x, conv_w, conv_b);

    gemm_kernel<<<NHW / 128, 256>>>(y, x, q_w, q_b, k_w, k_b, v_w, v_b);

    attn_kernel<<<NHW / 16, 512>>>(out);
}

// round 10
// speedup vs baseline: 1.6324x; 1.0962x over previous
#include <cuda_runtime.h>
#include <cuda_fp16.h>
#include <math.h>

#define N_IMG 2
#define C_IN 48
#define H 192
#define W 192
#define HW (H*W)          // 36864
#define NHW (N_IMG*HW)    // 73728
#define DIM 128
#define PE_DIM 48
#define SCALE 0.25f
#define TWO_PI 6.283185307179586f
#define EPS_F 1e-6f

#define WT_LD 56          // padded row length (halves) for Wt / As

// scratch
__device__ __half g_kv[(size_t)NHW * 256];  // [p][256]: 0:128 = k, 128:256 = v (fp16)
__device__ __half g_q [(size_t)NHW * 128];  // [p][128] (fp16, pre-scaled by SCALE)
__device__ float  g_pe[24 * NHW];           // [k][p] channel-major PE of frac_x
__device__ int    g_x0[NHW];
__device__ float  g_pbk[4 * DIM];           // pb @ k_w  (no bias)
__device__ float  g_pbv[4 * DIM];           // pb @ v_w
__device__ __half g_wt[3][DIM * WT_LD];     // transposed fp16 weights Wt[o][c]
__device__ float  g_bs[3][DIM];             // biases (q pre-scaled)

__constant__ float c_inv_dt[12] = {
    1.0f, 0.46415888336127786f, 0.21544346900318834f, 0.1f,
    0.046415888336127774f, 0.021544346900318832f, 0.01f,
    0.0046415888336127786f, 0.0021544346900318834f, 0.001f,
    0.00046415888336127786f, 0.00021544346900318834f
};

__device__ __forceinline__ void mma16816(float* c, const unsigned* a, const unsigned* b) {
    asm volatile(
        "mma.sync.aligned.m16n8k16.row.col.f32.f16.f16.f32 "
        "{%0,%1,%2,%3}, {%4,%5,%6,%7}, {%8,%9}, {%0,%1,%2,%3};"
        : "+f"(c[0]), "+f"(c[1]), "+f"(c[2]), "+f"(c[3])
        : "r"(a[0]), "r"(a[1]), "r"(a[2]), "r"(a[3]), "r"(b[0]), "r"(b[1]));
}

// ---------------------------------------------------------------------------
// K0a: weight prep — transpose + fp16 convert; fold SCALE into q weights/bias
// grid 3 blocks x 128 threads (thread = output column o)
// ---------------------------------------------------------------------------
__global__ void wt_kernel(const float* __restrict__ qw, const float* __restrict__ qb,
                          const float* __restrict__ kw, const float* __restrict__ kb,
                          const float* __restrict__ vw, const float* __restrict__ vb) {
    int mat = blockIdx.x;
    int o = threadIdx.x;
    const float* Wm = (mat == 0) ? kw : (mat == 1) ? vw : qw;
    const float* bm = (mat == 0) ? kb : (mat == 1) ? vb : qb;
    float sc = (mat == 2) ? SCALE : 1.0f;
    #pragma unroll
    for (int c = 0; c < 48; c++)
        g_wt[mat][o * WT_LD + c] = __float2half(Wm[c * DIM + o] * sc);
    #pragma unroll
    for (int c = 48; c < WT_LD; c++)
        g_wt[mat][o * WT_LD + c] = __float2half(0.0f);
    g_bs[mat][o] = bm[o] * sc;
}

// ---------------------------------------------------------------------------
// K0b: window-position-bias projected through k_w / v_w
// ---------------------------------------------------------------------------
__global__ void pb_kernel(const float* __restrict__ kw, const float* __restrict__ vw) {
    int o = threadIdx.x;  // 0..127
    int j = blockIdx.x;   // 0..3
    float dy = (float)(j >> 1);
    float dx = (float)(j & 1);
    float yv_ = dy / (1.0f + EPS_F) * TWO_PI;
    float xv_ = dx / (1.0f + EPS_F) * TWO_PI;
    float acck = 0.0f, accv = 0.0f;
    #pragma unroll
    for (int m = 0; m < 12; m++) {
        float sy, cy, sx, cx;
        __sincosf(yv_ * c_inv_dt[m], &sy, &cy);
        __sincosf(xv_ * c_inv_dt[m], &sx, &cx);
        acck += sy * kw[(2*m)*DIM + o]    + cy * kw[(2*m+1)*DIM + o]
              + sx * kw[(24+2*m)*DIM + o] + cx * kw[(25+2*m)*DIM + o];
        accv += sy * vw[(2*m)*DIM + o]    + cy * vw[(2*m+1)*DIM + o]
              + sx * vw[(24+2*m)*DIM + o] + cx * vw[(25+2*m)*DIM + o];
    }
    g_pbk[j*DIM + o] = acck;
    g_pbv[j*DIM + o] = accv;
}

// ---------------------------------------------------------------------------
// K1: 3x3 conv (96ch -> 1) => offset; writes floor index + PE(frac_x)
// ---------------------------------------------------------------------------
__global__ void conv_kernel(const float* __restrict__ y, const float* __restrict__ x,
                            const float* __restrict__ cw, const float* __restrict__ cb) {
    __shared__ float sw[96 * 9];
    int tid = threadIdx.y * 32 + threadIdx.x;
    for (int i = tid; i < 96 * 9; i += 256) sw[i] = cw[i];
    __syncthreads();

    int w0 = blockIdx.x * 32 + threadIdx.x;
    int h0 = blockIdx.y * 8 + threadIdx.y;
    int n  = blockIdx.z;

    const float* ybase = y + (size_t)n * C_IN * HW;
    const float* xbase = x + (size_t)n * C_IN * HW;

    float acc = cb[0];
    for (int ic = 0; ic < 96; ic++) {
        const float* src = (ic < 48) ? (ybase + ic * HW) : (xbase + (ic - 48) * HW);
        const float* wr = &sw[ic * 9];
        #pragma unroll
        for (int kh = 0; kh < 3; kh++) {
            int hh = h0 + kh - 1;
            if (hh < 0 || hh >= H) continue;
            const float* row = src + hh * W;
            #pragma unroll
            for (int kx = 0; kx < 3; kx++) {
                int ww = w0 + kx - 1;
                if (ww < 0 || ww >= W) continue;
                acc += row[ww] * wr[kh * 3 + kx];
            }
        }
    }
    float offv = acc * (2.0f / (float)W);
    float gx = (float)w0 + offv;
    float fl = floorf(gx);
    int p = n * HW + h0 * W + w0;
    g_x0[p] = (int)fl;
    float xe = (gx - fl) * (TWO_PI / (2.0f + EPS_F));
    #pragma unroll
    for (int m = 0; m < 12; m++) {
        float s, c;
        __sincosf(xe * c_inv_dt[m], &s, &c);
        g_pe[(2*m)   * NHW + p] = s;
        g_pe[(2*m+1) * NHW + p] = c;
    }
}

// ---------------------------------------------------------------------------
// K2: tensor-core GEMM. grid (NHW/128, 3): mat 0=k, 1=v (A=y), 2=q (A=x+PE).
// Block: 128 pixels x 128 outputs, K=48. 256 threads = 8 warps, warp 32x64.
// mma.sync.m16n8k16 fp16->fp32, fragments via direct LDS (56-half row pad).
// ---------------------------------------------------------------------------
__global__ void __launch_bounds__(256) gemm_kernel(
        const float* __restrict__ y, const float* __restrict__ x) {
    __shared__ __half As[128][WT_LD];   // 14 KB  (pixel-major A, fp16)
    __shared__ __half Ws[128][WT_LD];   // 14 KB  (Wt[o][c], fp16)
    __shared__ float  sbias[128];

    int tid = threadIdx.x;
    int mat = blockIdx.y;
    int p0 = blockIdx.x * 128;
    int n = p0 / HW;
    int hw0 = p0 - n * HW;

    // ---- load A tile: 2 threads per pixel, 24 channels each ----
    {
        int i = tid & 127;
        int half_sel = tid >> 7;           // 0 or 1
        int cbase = half_sel * 24;
        const float* src = ((mat < 2) ? y : x) + (size_t)n * C_IN * HW + hw0 + i;
        int p = p0 + i;
        #pragma unroll
        for (int cc = 0; cc < 12; cc++) {
            int c = cbase + cc * 2;
            float f0 = src[(size_t)c * HW];
            float f1 = src[(size_t)(c + 1) * HW];
            if (mat == 2) {
                if (c < 24) { f0 += (float)(c & 1); f1 += (float)((c + 1) & 1); }
                else {
                    f0 += g_pe[(c - 24) * NHW + p];
                    f1 += g_pe[(c - 23) * NHW + p];
                }
            }
            *(__half2*)&As[i][c] = __floats2half2_rn(f0, f1);
        }
    }

    // ---- load W tile (linear copy, 8B chunks) + bias ----
    {
        const uint2* src = (const uint2*)g_wt[mat];
        uint2* dst = (uint2*)&Ws[0][0];
        #pragma unroll
        for (int kk = 0; kk < 7; kk++)
            dst[tid + kk * 256] = src[tid + kk * 256];
        if (tid < 128) sbias[tid] = g_bs[mat][tid];
    }
    __syncthreads();

    int wid = tid >> 5, lane = tid & 31;
    int m0 = (wid & 3) * 32;
    int n0 = (wid >> 2) * 64;
    int qr = lane >> 2;          // 0..7
    int qc = 2 * (lane & 3);     // 0,2,4,6

    float acc[2][8][4];
    #pragma unroll
    for (int mm = 0; mm < 2; mm++)
        #pragma unroll
        for (int nb = 0; nb < 8; nb++)
            #pragma unroll
            for (int e = 0; e < 4; e++) acc[mm][nb][e] = 0.0f;

    #pragma unroll
    for (int k16 = 0; k16 < 3; k16++) {
        int kc = k16 * 16 + qc;
        unsigned afr[2][4];
        #pragma unroll
        for (int mm = 0; mm < 2; mm++) {
            int row = m0 + mm * 16 + qr;
            afr[mm][0] = *(const unsigned*)&As[row][kc];
            afr[mm][1] = *(const unsigned*)&As[row + 8][kc];
            afr[mm][2] = *(const unsigned*)&As[row][kc + 8];
            afr[mm][3] = *(const unsigned*)&As[row + 8][kc + 8];
        }
        #pragma unroll
        for (int nb = 0; nb < 8; nb++) {
            int o = n0 + nb * 8 + qr;
            unsigned bfr[2];
            bfr[0] = *(const unsigned*)&Ws[o][kc];
            bfr[1] = *(const unsigned*)&Ws[o][kc + 8];
            mma16816(acc[0][nb], afr[0], bfr);
            mma16816(acc[1][nb], afr[1], bfr);
        }
    }

    // ---- epilogue: add bias, convert to fp16, store ----
    __half* C; int ld, obase;
    if (mat == 2) { C = g_q + (size_t)p0 * 128; ld = 128; obase = 0; }
    else          { C = g_kv + (size_t)p0 * 256; ld = 256; obase = mat * 128; }
    #pragma unroll
    for (int mm = 0; mm < 2; mm++) {
        #pragma unroll
        for (int nb = 0; nb < 8; nb++) {
            int col = n0 + nb * 8 + qc;
            float b0 = sbias[col], b1 = sbias[col + 1];
            int r0 = m0 + mm * 16 + qr;
            __half2 v0 = __floats2half2_rn(acc[mm][nb][0] + b0, acc[mm][nb][1] + b1);
            __half2 v1 = __floats2half2_rn(acc[mm][nb][2] + b0, acc[mm][nb][3] + b1);
            *(__half2*)&C[(size_t)r0 * ld + obase + col]       = v0;
            *(__half2*)&C[(size_t)(r0 + 8) * ld + obase + col] = v1;
        }
    }
}

// ---------------------------------------------------------------------------
// K3: warp-per-pixel attention, lane owns 4 consecutive channels (c0=lane*4),
// fp16 kv/q loads (LDG.64), fp32 math, 2-shuffle head reduction.
// ---------------------------------------------------------------------------
typedef unsigned long long ull;
__global__ void __launch_bounds__(512) attn_kernel(float* __restrict__ out) {
    __shared__ float spbk[4][128];
    __shared__ float spbv[4][128];
    __shared__ float sout[128][17];

    int tid = threadIdx.x;
    spbk[tid >> 7][tid & 127] = g_pbk[tid];
    spbv[tid >> 7][tid & 127] = g_pbv[tid];
    __syncthreads();

    int w = tid >> 5;
    int lane = tid & 31;
    int p = blockIdx.x * 16 + w;
    int n = p / HW;
    int hw = p - n * HW;
    int gh = hw / W;
    int x0 = g_x0[p];

    int lin[4];
    #pragma unroll
    for (int j = 0; j < 4; j++) {
        int iy = min(max(gh + (j >> 1), 0), H - 1);
        int ix = min(max(x0 + (j & 1),  0), W - 1);
        lin[j] = n * HW + iy * W + ix;
    }

    int c0 = lane * 4;  // head = lane>>2

    float4 q4;
    {
        ull qq = *(const ull*)&g_q[(size_t)p * 128 + c0];
        float2 f0 = __half22float2(((const __half2*)&qq)[0]);
        float2 f1 = __half22float2(((const __half2*)&qq)[1]);
        q4 = make_float4(f0.x, f0.y, f1.x, f1.y);
    }

    float s[4];
    float4 v4[4];
    #pragma unroll
    for (int j = 0; j < 4; j++) {
        const __half* r = g_kv + (size_t)lin[j] * 256;
        ull kk = *(const ull*)&r[c0];
        ull vv = *(const ull*)&r[128 + c0];
        float2 k0 = __half22float2(((const __half2*)&kk)[0]);
        float2 k1 = __half22float2(((const __half2*)&kk)[1]);
        float2 w0 = __half22float2(((const __half2*)&vv)[0]);
        float2 w1 = __half22float2(((const __half2*)&vv)[1]);
        float4 pk = *(const float4*)&spbk[j][c0];
        float4 pv = *(const float4*)&spbv[j][c0];
        v4[j].x = w0.x + pv.x; v4[j].y = w0.y + pv.y;
        v4[j].z = w1.x + pv.z; v4[j].w = w1.y + pv.w;
        float part = q4.x * (k0.x + pk.x) + q4.y * (k0.y + pk.y)
                   + q4.z * (k1.x + pk.z) + q4.w * (k1.y + pk.w);
        part += __shfl_xor_sync(0xffffffffu, part, 1);
        part += __shfl_xor_sync(0xffffffffu, part, 2);
        s[j] = part;
    }

    float mx = fmaxf(fmaxf(s[0], s[1]), fmaxf(s[2], s[3]));
    float e0 = __expf(s[0] - mx), e1 = __expf(s[1] - mx);
    float e2 = __expf(s[2] - mx), e3 = __expf(s[3] - mx);
    float inv = 1.0f / (e0 + e1 + e2 + e3);
    float a0 = e0 * inv, a1 = e1 * inv, a2 = e2 * inv, a3 = e3 * inv;

    sout[c0 + 0][w] = a0 * v4[0].x + a1 * v4[1].x + a2 * v4[2].x + a3 * v4[3].x;
    sout[c0 + 1][w] = a0 * v4[0].y + a1 * v4[1].y + a2 * v4[2].y + a3 * v4[3].y;
    sout[c0 + 2][w] = a0 * v4[0].z + a1 * v4[1].z + a2 * v4[2].z + a3 * v4[3].z;
    sout[c0 + 3][w] = a0 * v4[0].w + a1 * v4[1].w + a2 * v4[2].w + a3 * v4[3].w;
    __syncthreads();

    int p0 = blockIdx.x * 16;
    int n0 = p0 / HW;
    int hw0 = p0 - n0 * HW;
    int ch = tid >> 2;
    int px = (tid & 3) * 4;
    float4 v = make_float4(sout[ch][px], sout[ch][px + 1], sout[ch][px + 2], sout[ch][px + 3]);
    *(float4*)&out[(size_t)n0 * DIM * HW + (size_t)ch * HW + hw0 + px] = v;
}

// ---------------------------------------------------------------------------
extern "C" void kernel_launch(void* const* d_in, const int* in_sizes, int n_in,
                              void* d_out, int out_size) {
    const float* y      = (const float*)d_in[0];
    const float* x      = (const float*)d_in[1];
    const float* conv_w = (const float*)d_in[2];
    const float* conv_b = (const float*)d_in[3];
    const float* q_w    = (const float*)d_in[4];
    const float* q_b    = (const float*)d_in[5];
    const float* k_w    = (const float*)d_in[6];
    const float* k_b    = (const float*)d_in[7];
    const float* v_w    = (const float*)d_in[8];
    const float* v_b    = (const float*)d_in[9];
    float* out = (float*)d_out;

    wt_kernel<<<3, 128>>>(q_w, q_b, k_w, k_b, v_w, v_b);
    pb_kernel<<<4, 128>>>(k_w, v_w);

    dim3 cgrid(W / 32, H / 8, N_IMG);
    dim3 cblk(32, 8);
    conv_kernel<<<cgrid, cblk>>>(y, x, conv_w, conv_b);

    dim3 ggrid(NHW / 128, 3);
    gemm_kernel<<<ggrid, 256>>>(y, x);

    attn_kernel<<<NHW / 16, 512>>>(out);
}

// round 12
// speedup vs baseline: 1.6748x; 1.0260x over previous
#include <cuda_runtime.h>
#include <cuda_fp16.h>
#include <math.h>

#define N_IMG 2
#define C_IN 48
#define H 192
#define W 192
#define HW (H*W)          // 36864
#define NHW (N_IMG*HW)    // 73728
#define DIM 128
#define PE_DIM 48
#define SCALE 0.25f
#define TWO_PI 6.283185307179586f
#define EPS_F 1e-6f

#define WT_LD 56          // padded row length (halves) for Wt / As

// scratch
__device__ __half g_kv[(size_t)NHW * 256];  // [p][256]: 0:128 = k, 128:256 = v (fp16)
__device__ __half g_q [(size_t)NHW * 128];  // [p][128] (fp16, pre-scaled by SCALE)
__device__ float  g_pe[24 * NHW];           // [k][p] channel-major PE of frac_x
__device__ int    g_x0[NHW];
__device__ float  g_pbk[4 * DIM];           // pb @ k_w  (no bias)
__device__ float  g_pbv[4 * DIM];           // pb @ v_w
__device__ __half g_wt[3][DIM * WT_LD];     // transposed fp16 weights Wt[o][c]
__device__ float  g_bs[3][DIM];             // biases (q pre-scaled)

__constant__ float c_inv_dt[12] = {
    1.0f, 0.46415888336127786f, 0.21544346900318834f, 0.1f,
    0.046415888336127774f, 0.021544346900318832f, 0.01f,
    0.0046415888336127786f, 0.0021544346900318834f, 0.001f,
    0.00046415888336127786f, 0.00021544346900318834f
};

__device__ __forceinline__ void mma16816(float* c, const unsigned* a, const unsigned* b) {
    asm volatile(
        "mma.sync.aligned.m16n8k16.row.col.f32.f16.f16.f32 "
        "{%0,%1,%2,%3}, {%4,%5,%6,%7}, {%8,%9}, {%0,%1,%2,%3};"
        : "+f"(c[0]), "+f"(c[1]), "+f"(c[2]), "+f"(c[3])
        : "r"(a[0]), "r"(a[1]), "r"(a[2]), "r"(a[3]), "r"(b[0]), "r"(b[1]));
}

// ---------------------------------------------------------------------------
// K0a: weight prep — transpose + fp16 convert; fold SCALE into q weights/bias
// ---------------------------------------------------------------------------
__global__ void wt_kernel(const float* __restrict__ qw, const float* __restrict__ qb,
                          const float* __restrict__ kw, const float* __restrict__ kb,
                          const float* __restrict__ vw, const float* __restrict__ vb) {
    int mat = blockIdx.x;
    int o = threadIdx.x;
    const float* Wm = (mat == 0) ? kw : (mat == 1) ? vw : qw;
    const float* bm = (mat == 0) ? kb : (mat == 1) ? vb : qb;
    float sc = (mat == 2) ? SCALE : 1.0f;
    #pragma unroll
    for (int c = 0; c < 48; c++)
        g_wt[mat][o * WT_LD + c] = __float2half(Wm[c * DIM + o] * sc);
    #pragma unroll
    for (int c = 48; c < WT_LD; c++)
        g_wt[mat][o * WT_LD + c] = __float2half(0.0f);
    g_bs[mat][o] = bm[o] * sc;
}

// ---------------------------------------------------------------------------
// K0b: window-position-bias projected through k_w / v_w
// ---------------------------------------------------------------------------
__global__ void pb_kernel(const float* __restrict__ kw, const float* __restrict__ vw) {
    int o = threadIdx.x;  // 0..127
    int j = blockIdx.x;   // 0..3
    float dy = (float)(j >> 1);
    float dx = (float)(j & 1);
    float yv_ = dy / (1.0f + EPS_F) * TWO_PI;
    float xv_ = dx / (1.0f + EPS_F) * TWO_PI;
    float acck = 0.0f, accv = 0.0f;
    #pragma unroll
    for (int m = 0; m < 12; m++) {
        float sy, cy, sx, cx;
        __sincosf(yv_ * c_inv_dt[m], &sy, &cy);
        __sincosf(xv_ * c_inv_dt[m], &sx, &cx);
        acck += sy * kw[(2*m)*DIM + o]    + cy * kw[(2*m+1)*DIM + o]
              + sx * kw[(24+2*m)*DIM + o] + cx * kw[(25+2*m)*DIM + o];
        accv += sy * vw[(2*m)*DIM + o]    + cy * vw[(2*m+1)*DIM + o]
              + sx * vw[(24+2*m)*DIM + o] + cx * vw[(25+2*m)*DIM + o];
    }
    g_pbk[j*DIM + o] = acck;
    g_pbv[j*DIM + o] = accv;
}

// ---------------------------------------------------------------------------
// K1: smem-tiled 3x3 conv (96ch -> 1) => offset; floor index + PE(frac_x).
// Block 32x8 pixels; per channel cooperative 34x10 halo tile load.
// ---------------------------------------------------------------------------
__global__ void __launch_bounds__(256) conv_kernel(
        const float* __restrict__ y, const float* __restrict__ x,
        const float* __restrict__ cw, const float* __restrict__ cb) {
    __shared__ float sw[96 * 9];
    __shared__ float tile[10][34];

    int tid = threadIdx.y * 32 + threadIdx.x;
    for (int i = tid; i < 96 * 9; i += 256) sw[i] = cw[i];

    int w0base = blockIdx.x * 32;
    int h0base = blockIdx.y * 8;
    int n = blockIdx.z;

    const float* ybase = y + (size_t)n * C_IN * HW;
    const float* xbase = x + (size_t)n * C_IN * HW;

    float acc = cb[0];
    __syncthreads();

    #pragma unroll 1
    for (int ic = 0; ic < 96; ic++) {
        const float* src = (ic < 48) ? (ybase + (size_t)ic * HW)
                                     : (xbase + (size_t)(ic - 48) * HW);
        // cooperative halo load: 10 rows x 34 cols
        #pragma unroll
        for (int idx = tid; idx < 340; idx += 256) {
            int r = idx / 34, cc = idx - r * 34;
            int hh = h0base + r - 1;
            int ww = w0base + cc - 1;
            float v = 0.0f;
            if (hh >= 0 && hh < H && ww >= 0 && ww < W) v = src[hh * W + ww];
            tile[r][cc] = v;
        }
        __syncthreads();

        const float* wr = &sw[ic * 9];
        #pragma unroll
        for (int kh = 0; kh < 3; kh++) {
            float t0 = tile[threadIdx.y + kh][threadIdx.x];
            float t1 = tile[threadIdx.y + kh][threadIdx.x + 1];
            float t2 = tile[threadIdx.y + kh][threadIdx.x + 2];
            acc += t0 * wr[kh * 3] + t1 * wr[kh * 3 + 1] + t2 * wr[kh * 3 + 2];
        }
        __syncthreads();
    }

    int w0 = w0base + threadIdx.x;
    int h0 = h0base + threadIdx.y;
    float offv = acc * (2.0f / (float)W);
    float gx = (float)w0 + offv;
    float fl = floorf(gx);
    int p = n * HW + h0 * W + w0;
    g_x0[p] = (int)fl;
    float xe = (gx - fl) * (TWO_PI / (2.0f + EPS_F));
    #pragma unroll
    for (int m = 0; m < 12; m++) {
        float s, c;
        __sincosf(xe * c_inv_dt[m], &s, &c);
        g_pe[(2*m)   * NHW + p] = s;
        g_pe[(2*m+1) * NHW + p] = c;
    }
}

// ---------------------------------------------------------------------------
// K2: tensor-core GEMM. grid (NHW/128, 3): mat 0=k, 1=v (A=y), 2=q (A=x+PE).
// Block: 128 pixels x 128 outputs, K=48. 256 threads = 8 warps, warp 32x64.
// ---------------------------------------------------------------------------
__global__ void __launch_bounds__(256) gemm_kernel(
        const float* __restrict__ y, const float* __restrict__ x) {
    __shared__ __half As[128][WT_LD];   // 14 KB
    __shared__ __half Ws[128][WT_LD];   // 14 KB
    __shared__ float  sbias[128];

    int tid = threadIdx.x;
    int mat = blockIdx.y;
    int p0 = blockIdx.x * 128;
    int n = p0 / HW;
    int hw0 = p0 - n * HW;

    // ---- load A tile: 2 threads per pixel, 24 channels each ----
    {
        int i = tid & 127;
        int half_sel = tid >> 7;
        int cbase = half_sel * 24;
        const float* src = ((mat < 2) ? y : x) + (size_t)n * C_IN * HW + hw0 + i;
        int p = p0 + i;
        #pragma unroll
        for (int cc = 0; cc < 12; cc++) {
            int c = cbase + cc * 2;
            float f0 = src[(size_t)c * HW];
            float f1 = src[(size_t)(c + 1) * HW];
            if (mat == 2) {
                if (c < 24) { f0 += (float)(c & 1); f1 += (float)((c + 1) & 1); }
                else {
                    f0 += g_pe[(c - 24) * NHW + p];
                    f1 += g_pe[(c - 23) * NHW + p];
                }
            }
            *(__half2*)&As[i][c] = __floats2half2_rn(f0, f1);
        }
    }

    // ---- load W tile + bias ----
    {
        const uint2* src = (const uint2*)g_wt[mat];
        uint2* dst = (uint2*)&Ws[0][0];
        #pragma unroll
        for (int kk = 0; kk < 7; kk++)
            dst[tid + kk * 256] = src[tid + kk * 256];
        if (tid < 128) sbias[tid] = g_bs[mat][tid];
    }
    __syncthreads();

    int wid = tid >> 5, lane = tid & 31;
    int m0 = (wid & 3) * 32;
    int n0 = (wid >> 2) * 64;
    int qr = lane >> 2;
    int qc = 2 * (lane & 3);

    float acc[2][8][4];
    #pragma unroll
    for (int mm = 0; mm < 2; mm++)
        #pragma unroll
        for (int nb = 0; nb < 8; nb++)
            #pragma unroll
            for (int e = 0; e < 4; e++) acc[mm][nb][e] = 0.0f;

    #pragma unroll
    for (int k16 = 0; k16 < 3; k16++) {
        int kc = k16 * 16 + qc;
        unsigned afr[2][4];
        #pragma unroll
        for (int mm = 0; mm < 2; mm++) {
            int row = m0 + mm * 16 + qr;
            afr[mm][0] = *(const unsigned*)&As[row][kc];
            afr[mm][1] = *(const unsigned*)&As[row + 8][kc];
            afr[mm][2] = *(const unsigned*)&As[row][kc + 8];
            afr[mm][3] = *(const unsigned*)&As[row + 8][kc + 8];
        }
        #pragma unroll
        for (int nb = 0; nb < 8; nb++) {
            int o = n0 + nb * 8 + qr;
            unsigned bfr[2];
            bfr[0] = *(const unsigned*)&Ws[o][kc];
            bfr[1] = *(const unsigned*)&Ws[o][kc + 8];
            mma16816(acc[0][nb], afr[0], bfr);
            mma16816(acc[1][nb], afr[1], bfr);
        }
    }

    __half* C; int ld, obase;
    if (mat == 2) { C = g_q + (size_t)p0 * 128; ld = 128; obase = 0; }
    else          { C = g_kv + (size_t)p0 * 256; ld = 256; obase = mat * 128; }
    #pragma unroll
    for (int mm = 0; mm < 2; mm++) {
        #pragma unroll
        for (int nb = 0; nb < 8; nb++) {
            int col = n0 + nb * 8 + qc;
            float b0 = sbias[col], b1 = sbias[col + 1];
            int r0 = m0 + mm * 16 + qr;
            __half2 v0 = __floats2half2_rn(acc[mm][nb][0] + b0, acc[mm][nb][1] + b1);
            __half2 v1 = __floats2half2_rn(acc[mm][nb][2] + b0, acc[mm][nb][3] + b1);
            *(__half2*)&C[(size_t)r0 * ld + obase + col]       = v0;
            *(__half2*)&C[(size_t)(r0 + 8) * ld + obase + col] = v1;
        }
    }
}

// ---------------------------------------------------------------------------
// K3: warp-per-pixel attention, lane owns 4 consecutive channels.
// ---------------------------------------------------------------------------
typedef unsigned long long ull;
__global__ void __launch_bounds__(512) attn_kernel(float* __restrict__ out) {
    __shared__ float spbk[4][128];
    __shared__ float spbv[4][128];
    __shared__ float sout[128][17];

    int tid = threadIdx.x;
    spbk[tid >> 7][tid & 127] = g_pbk[tid];
    spbv[tid >> 7][tid & 127] = g_pbv[tid];
    __syncthreads();

    int w = tid >> 5;
    int lane = tid & 31;
    int p = blockIdx.x * 16 + w;
    int n = p / HW;
    int hw = p - n * HW;
    int gh = hw / W;
    int x0 = g_x0[p];

    int lin[4];
    #pragma unroll
    for (int j = 0; j < 4; j++) {
        int iy = min(max(gh + (j >> 1), 0), H - 1);
        int ix = min(max(x0 + (j & 1),  0), W - 1);
        lin[j] = n * HW + iy * W + ix;
    }

    int c0 = lane * 4;

    float4 q4;
    {
        ull qq = *(const ull*)&g_q[(size_t)p * 128 + c0];
        float2 f0 = __half22float2(((const __half2*)&qq)[0]);
        float2 f1 = __half22float2(((const __half2*)&qq)[1]);
        q4 = make_float4(f0.x, f0.y, f1.x, f1.y);
    }

    float s[4];
    float4 v4[4];
    #pragma unroll
    for (int j = 0; j < 4; j++) {
        const __half* r = g_kv + (size_t)lin[j] * 256;
        ull kk = *(const ull*)&r[c0];
        ull vv = *(const ull*)&r[128 + c0];
        float2 k0 = __half22float2(((const __half2*)&kk)[0]);
        float2 k1 = __half22float2(((const __half2*)&kk)[1]);
        float2 w0 = __half22float2(((const __half2*)&vv)[0]);
        float2 w1 = __half22float2(((const __half2*)&vv)[1]);
        float4 pk = *(const float4*)&spbk[j][c0];
        float4 pv = *(const float4*)&spbv[j][c0];
        v4[j].x = w0.x + pv.x; v4[j].y = w0.y + pv.y;
        v4[j].z = w1.x + pv.z; v4[j].w = w1.y + pv.w;
        float part = q4.x * (k0.x + pk.x) + q4.y * (k0.y + pk.y)
                   + q4.z * (k1.x + pk.z) + q4.w * (k1.y + pk.w);
        part += __shfl_xor_sync(0xffffffffu, part, 1);
        part += __shfl_xor_sync(0xffffffffu, part, 2);
        s[j] = part;
    }

    float mx = fmaxf(fmaxf(s[0], s[1]), fmaxf(s[2], s[3]));
    float e0 = __expf(s[0] - mx), e1 = __expf(s[1] - mx);
    float e2 = __expf(s[2] - mx), e3 = __expf(s[3] - mx);
    float inv = 1.0f / (e0 + e1 + e2 + e3);
    float a0 = e0 * inv, a1 = e1 * inv, a2 = e2 * inv, a3 = e3 * inv;

    sout[c0 + 0][w] = a0 * v4[0].x + a1 * v4[1].x + a2 * v4[2].x + a3 * v4[3].x;
    sout[c0 + 1][w] = a0 * v4[0].y + a1 * v4[1].y + a2 * v4[2].y + a3 * v4[3].y;
    sout[c0 + 2][w] = a0 * v4[0].z + a1 * v4[1].z + a2 * v4[2].z + a3 * v4[3].z;
    sout[c0 + 3][w] = a0 * v4[0].w + a1 * v4[1].w + a2 * v4[2].w + a3 * v4[3].w;
    __syncthreads();

    int p0 = blockIdx.x * 16;
    int n0 = p0 / HW;
    int hw0 = p0 - n0 * HW;
    int ch = tid >> 2;
    int px = (tid & 3) * 4;
    float4 v = make_float4(sout[ch][px], sout[ch][px + 1], sout[ch][px + 2], sout[ch][px + 3]);
    *(float4*)&out[(size_t)n0 * DIM * HW + (size_t)ch * HW + hw0 + px] = v;
}

// ---------------------------------------------------------------------------
extern "C" void kernel_launch(void* const* d_in, const int* in_sizes, int n_in,
                              void* d_out, int out_size) {
    const float* y      = (const float*)d_in[0];
    const float* x      = (const float*)d_in[1];
    const float* conv_w = (const float*)d_in[2];
    const float* conv_b = (const float*)d_in[3];
    const float* q_w    = (const float*)d_in[4];
    const float* q_b    = (const float*)d_in[5];
    const float* k_w    = (const float*)d_in[6];
    const float* k_b    = (const float*)d_in[7];
    const float* v_w    = (const float*)d_in[8];
    const float* v_b    = (const float*)d_in[9];
    float* out = (float*)d_out;

    wt_kernel<<<3, 128>>>(q_w, q_b, k_w, k_b, v_w, v_b);
    pb_kernel<<<4, 128>>>(k_w, v_w);

    dim3 cgrid(W / 32, H / 8, N_IMG);
    dim3 cblk(32, 8);
    conv_kernel<<<cgrid, cblk>>>(y, x, conv_w, conv_b);

    dim3 ggrid(NHW / 128, 3);
    gemm_kernel<<<ggrid, 256>>>(y, x);

    attn_kernel<<<NHW / 16, 512>>>(out);
}

// round 13
// speedup vs baseline: 2.6243x; 1.5669x over previous
#include <cuda_runtime.h>
#include <cuda_fp16.h>
#include <math.h>

#define N_IMG 2
#define C_IN 48
#define H 192
#define W 192
#define HW (H*W)          // 36864
#define NHW (N_IMG*HW)    // 73728
#define DIM 128
#define PE_DIM 48
#define SCALE 0.25f
#define TWO_PI 6.283185307179586f
#define EPS_F 1e-6f

#define WT_LD 56          // padded row length (halves) for Wt / As
#define CS_LD 136         // padded C-staging row (halves)

// scratch
__device__ __half g_kv[(size_t)NHW * 256];  // [p][256]: 0:128 = k, 128:256 = v (fp16)
__device__ __half g_q [(size_t)NHW * 128];  // [p][128] (fp16, pre-scaled by SCALE)
__device__ float  g_pe[24 * NHW];           // [k][p] channel-major PE of frac_x
__device__ int    g_x0[NHW];
__device__ float  g_off4[4 * NHW];          // conv partial sums per channel slab
__device__ float  g_pbk[4 * DIM];           // pb @ k_w  (no bias)
__device__ float  g_pbv[4 * DIM];           // pb @ v_w
__device__ __half g_wt[3][DIM * WT_LD];     // transposed fp16 weights Wt[o][c]
__device__ float  g_bs[3][DIM];             // biases (q pre-scaled)

__constant__ float c_inv_dt[12] = {
    1.0f, 0.46415888336127786f, 0.21544346900318834f, 0.1f,
    0.046415888336127774f, 0.021544346900318832f, 0.01f,
    0.0046415888336127786f, 0.0021544346900318834f, 0.001f,
    0.00046415888336127786f, 0.00021544346900318834f
};

__device__ __forceinline__ void mma16816(float* c, const unsigned* a, const unsigned* b) {
    asm volatile(
        "mma.sync.aligned.m16n8k16.row.col.f32.f16.f16.f32 "
        "{%0,%1,%2,%3}, {%4,%5,%6,%7}, {%8,%9}, {%0,%1,%2,%3};"
        : "+f"(c[0]), "+f"(c[1]), "+f"(c[2]), "+f"(c[3])
        : "r"(a[0]), "r"(a[1]), "r"(a[2]), "r"(a[3]), "r"(b[0]), "r"(b[1]));
}

// ---------------------------------------------------------------------------
// K0: weight prep (blocks 0-2) + window-position-bias (blocks 3-6)
// ---------------------------------------------------------------------------
__global__ void wtpb_kernel(const float* __restrict__ qw, const float* __restrict__ qb,
                            const float* __restrict__ kw, const float* __restrict__ kb,
                            const float* __restrict__ vw, const float* __restrict__ vb) {
    int b = blockIdx.x;
    int o = threadIdx.x;  // 0..127
    if (b < 3) {
        int mat = b;
        const float* Wm = (mat == 0) ? kw : (mat == 1) ? vw : qw;
        const float* bm = (mat == 0) ? kb : (mat == 1) ? vb : qb;
        float sc = (mat == 2) ? SCALE : 1.0f;
        #pragma unroll
        for (int c = 0; c < 48; c++)
            g_wt[mat][o * WT_LD + c] = __float2half(Wm[c * DIM + o] * sc);
        #pragma unroll
        for (int c = 48; c < WT_LD; c++)
            g_wt[mat][o * WT_LD + c] = __float2half(0.0f);
        g_bs[mat][o] = bm[o] * sc;
    } else {
        int j = b - 3;  // 0..3
        float dy = (float)(j >> 1);
        float dx = (float)(j & 1);
        float yv_ = dy / (1.0f + EPS_F) * TWO_PI;
        float xv_ = dx / (1.0f + EPS_F) * TWO_PI;
        float acck = 0.0f, accv = 0.0f;
        #pragma unroll
        for (int m = 0; m < 12; m++) {
            float sy, cy, sx, cx;
            __sincosf(yv_ * c_inv_dt[m], &sy, &cy);
            __sincosf(xv_ * c_inv_dt[m], &sx, &cx);
            acck += sy * kw[(2*m)*DIM + o]    + cy * kw[(2*m+1)*DIM + o]
                  + sx * kw[(24+2*m)*DIM + o] + cx * kw[(25+2*m)*DIM + o];
            accv += sy * vw[(2*m)*DIM + o]    + cy * vw[(2*m+1)*DIM + o]
                  + sx * vw[(24+2*m)*DIM + o] + cx * vw[(25+2*m)*DIM + o];
        }
        g_pbk[j*DIM + o] = acck;
        g_pbv[j*DIM + o] = accv;
    }
}

// ---------------------------------------------------------------------------
// K1a: conv partials — 4 channel slabs of 24, deterministic (no atomics).
// grid (6, 24, 8): z = n*4 + slab. Block 32x8 pixels, halo tile per channel.
// ---------------------------------------------------------------------------
__global__ void __launch_bounds__(256) conv_slab_kernel(
        const float* __restrict__ y, const float* __restrict__ x,
        const float* __restrict__ cw) {
    __shared__ float sw[24 * 9];
    __shared__ float tile[10][34];

    int tid = threadIdx.y * 32 + threadIdx.x;
    int slab = blockIdx.z & 3;
    int n = blockIdx.z >> 2;

    if (tid < 216) sw[tid] = cw[slab * 216 + tid];

    int w0base = blockIdx.x * 32;
    int h0base = blockIdx.y * 8;

    const float* src_base = ((slab < 2) ? y : x)
        + (size_t)n * C_IN * HW + (size_t)((slab & 1) * 24) * HW;

    float acc = 0.0f;
    __syncthreads();

    #pragma unroll 1
    for (int ic = 0; ic < 24; ic++) {
        const float* src = src_base + (size_t)ic * HW;
        #pragma unroll
        for (int idx = tid; idx < 340; idx += 256) {
            int r = idx / 34, cc = idx - r * 34;
            int hh = h0base + r - 1;
            int ww = w0base + cc - 1;
            float v = 0.0f;
            if (hh >= 0 && hh < H && ww >= 0 && ww < W) v = src[hh * W + ww];
            tile[r][cc] = v;
        }
        __syncthreads();
        const float* wr = &sw[ic * 9];
        #pragma unroll
        for (int kh = 0; kh < 3; kh++) {
            float t0 = tile[threadIdx.y + kh][threadIdx.x];
            float t1 = tile[threadIdx.y + kh][threadIdx.x + 1];
            float t2 = tile[threadIdx.y + kh][threadIdx.x + 2];
            acc += t0 * wr[kh * 3] + t1 * wr[kh * 3 + 1] + t2 * wr[kh * 3 + 2];
        }
        __syncthreads();
    }

    int p = n * HW + (h0base + threadIdx.y) * W + w0base + threadIdx.x;
    g_off4[slab * NHW + p] = acc;
}

// ---------------------------------------------------------------------------
// K1b: finalize — fixed-order sum of slabs, offset -> floor index + PE(frac)
// ---------------------------------------------------------------------------
__global__ void __launch_bounds__(256) finalize_kernel(const float* __restrict__ cb) {
    int p = blockIdx.x * 256 + threadIdx.x;   // 288 * 256 = NHW
    float s01 = g_off4[p] + g_off4[NHW + p];
    float s23 = g_off4[2 * NHW + p] + g_off4[3 * NHW + p];
    float offv = (s01 + s23 + cb[0]) * (2.0f / (float)W);
    int hw = p % HW;
    int w0 = hw % W;
    float gx = (float)w0 + offv;
    float fl = floorf(gx);
    g_x0[p] = (int)fl;
    float xe = (gx - fl) * (TWO_PI / (2.0f + EPS_F));
    #pragma unroll
    for (int m = 0; m < 12; m++) {
        float s, c;
        __sincosf(xe * c_inv_dt[m], &s, &c);
        g_pe[(2*m)   * NHW + p] = s;
        g_pe[(2*m+1) * NHW + p] = c;
    }
}

// ---------------------------------------------------------------------------
// K2: tensor-core GEMM. grid (NHW/128, 2). by=0: k AND v from y (A loaded
// once, two weight passes). by=1: q from x+PE. C staged through smem for
// coalesced 128B stores. 256 threads = 8 warps, warp 32x64.
// ---------------------------------------------------------------------------
__global__ void __launch_bounds__(256) gemm_kernel(
        const float* __restrict__ y, const float* __restrict__ x) {
    extern __shared__ char dynsmem[];
    __half (*As)[WT_LD] = (__half(*)[WT_LD])dynsmem;                    // 14336 B
    __half (*Ws)[WT_LD] = (__half(*)[WT_LD])(dynsmem + 14336);         // 14336 B
    __half (*Cs)[CS_LD] = (__half(*)[CS_LD])(dynsmem + 28672);         // 34816 B
    float* sbias = (float*)(dynsmem + 28672 + 34816);                  // 512 B

    int tid = threadIdx.x;
    int by = blockIdx.y;            // 0 = k&v, 1 = q
    int p0 = blockIdx.x * 128;
    int n = p0 / HW;
    int hw0 = p0 - n * HW;

    // ---- load A tile: 2 threads per pixel, 24 channels each ----
    {
        int i = tid & 127;
        int half_sel = tid >> 7;
        int cbase = half_sel * 24;
        const float* src = ((by == 0) ? y : x) + (size_t)n * C_IN * HW + hw0 + i;
        int p = p0 + i;
        #pragma unroll
        for (int cc = 0; cc < 12; cc++) {
            int c = cbase + cc * 2;
            float f0 = src[(size_t)c * HW];
            float f1 = src[(size_t)(c + 1) * HW];
            if (by == 1) {
                if (c < 24) { f0 += (float)(c & 1); f1 += (float)((c + 1) & 1); }
                else {
                    f0 += g_pe[(c - 24) * NHW + p];
                    f1 += g_pe[(c - 23) * NHW + p];
                }
            }
            *(__half2*)&As[i][c] = __floats2half2_rn(f0, f1);
        }
    }

    int wid = tid >> 5, lane = tid & 31;
    int m0 = (wid & 3) * 32;
    int n0 = (wid >> 2) * 64;
    int qr = lane >> 2;
    int qc = 2 * (lane & 3);

    int nmats = (by == 0) ? 2 : 1;

    #pragma unroll 1
    for (int mi = 0; mi < nmats; mi++) {
        int mat = (by == 0) ? mi : 2;

        // load weight tile + bias (Ws overwrite guarded by loop-end barrier)
        {
            const uint2* src = (const uint2*)g_wt[mat];
            uint2* dst = (uint2*)&Ws[0][0];
            #pragma unroll
            for (int kk = 0; kk < 7; kk++)
                dst[tid + kk * 256] = src[tid + kk * 256];
            if (tid < 128) sbias[tid] = g_bs[mat][tid];
        }
        __syncthreads();

        float acc[2][8][4];
        #pragma unroll
        for (int mm = 0; mm < 2; mm++)
            #pragma unroll
            for (int nb = 0; nb < 8; nb++)
                #pragma unroll
                for (int e = 0; e < 4; e++) acc[mm][nb][e] = 0.0f;

        #pragma unroll
        for (int k16 = 0; k16 < 3; k16++) {
            int kc = k16 * 16 + qc;
            unsigned afr[2][4];
            #pragma unroll
            for (int mm = 0; mm < 2; mm++) {
                int row = m0 + mm * 16 + qr;
                afr[mm][0] = *(const unsigned*)&As[row][kc];
                afr[mm][1] = *(const unsigned*)&As[row + 8][kc];
                afr[mm][2] = *(const unsigned*)&As[row][kc + 8];
                afr[mm][3] = *(const unsigned*)&As[row + 8][kc + 8];
            }
            #pragma unroll
            for (int nb = 0; nb < 8; nb++) {
                int o = n0 + nb * 8 + qr;
                unsigned bfr[2];
                bfr[0] = *(const unsigned*)&Ws[o][kc];
                bfr[1] = *(const unsigned*)&Ws[o][kc + 8];
                mma16816(acc[0][nb], afr[0], bfr);
                mma16816(acc[1][nb], afr[1], bfr);
            }
        }

        // epilogue: bias + fp16 into Cs (conflict-free via CS_LD pad)
        #pragma unroll
        for (int mm = 0; mm < 2; mm++) {
            #pragma unroll
            for (int nb = 0; nb < 8; nb++) {
                int col = n0 + nb * 8 + qc;
                float b0 = sbias[col], b1 = sbias[col + 1];
                int r0 = m0 + mm * 16 + qr;
                *(__half2*)&Cs[r0][col]     = __floats2half2_rn(acc[mm][nb][0] + b0, acc[mm][nb][1] + b1);
                *(__half2*)&Cs[r0 + 8][col] = __floats2half2_rn(acc[mm][nb][2] + b0, acc[mm][nb][3] + b1);
            }
        }
        __syncthreads();

        // coalesced store: 128 rows x 256B
        __half* C; int ld, obase;
        if (by == 1) { C = g_q + (size_t)p0 * 128; ld = 128; obase = 0; }
        else         { C = g_kv + (size_t)p0 * 256; ld = 256; obase = mat * 128; }
        #pragma unroll
        for (int it = 0; it < 8; it++) {
            int idx = tid + it * 256;
            int row = idx >> 4;
            int c16 = (idx & 15) * 8;
            uint4 vv = *(const uint4*)&Cs[row][c16];
            *(uint4*)&C[(size_t)row * ld + obase + c16] = vv;
        }
        __syncthreads();
    }
}

// ---------------------------------------------------------------------------
// K3: warp-per-pixel attention, lane owns 4 consecutive channels.
// ---------------------------------------------------------------------------
typedef unsigned long long ull;
__global__ void __launch_bounds__(512) attn_kernel(float* __restrict__ out) {
    __shared__ float spbk[4][128];
    __shared__ float spbv[4][128];
    __shared__ float sout[128][17];

    int tid = threadIdx.x;
    spbk[tid >> 7][tid & 127] = g_pbk[tid];
    spbv[tid >> 7][tid & 127] = g_pbv[tid];
    __syncthreads();

    int w = tid >> 5;
    int lane = tid & 31;
    int p = blockIdx.x * 16 + w;
    int n = p / HW;
    int hw = p - n * HW;
    int gh = hw / W;
    int x0 = g_x0[p];

    int lin[4];
    #pragma unroll
    for (int j = 0; j < 4; j++) {
        int iy = min(max(gh + (j >> 1), 0), H - 1);
        int ix = min(max(x0 + (j & 1),  0), W - 1);
        lin[j] = n * HW + iy * W + ix;
    }

    int c0 = lane * 4;

    float4 q4;
    {
        ull qq = *(const ull*)&g_q[(size_t)p * 128 + c0];
        float2 f0 = __half22float2(((const __half2*)&qq)[0]);
        float2 f1 = __half22float2(((const __half2*)&qq)[1]);
        q4 = make_float4(f0.x, f0.y, f1.x, f1.y);
    }

    float s[4];
    float4 v4[4];
    #pragma unroll
    for (int j = 0; j < 4; j++) {
        const __half* r = g_kv + (size_t)lin[j] * 256;
        ull kk = *(const ull*)&r[c0];
        ull vv = *(const ull*)&r[128 + c0];
        float2 k0 = __half22float2(((const __half2*)&kk)[0]);
        float2 k1 = __half22float2(((const __half2*)&kk)[1]);
        float2 w0 = __half22float2(((const __half2*)&vv)[0]);
        float2 w1 = __half22float2(((const __half2*)&vv)[1]);
        float4 pk = *(const float4*)&spbk[j][c0];
        float4 pv = *(const float4*)&spbv[j][c0];
        v4[j].x = w0.x + pv.x; v4[j].y = w0.y + pv.y;
        v4[j].z = w1.x + pv.z; v4[j].w = w1.y + pv.w;
        float part = q4.x * (k0.x + pk.x) + q4.y * (k0.y + pk.y)
                   + q4.z * (k1.x + pk.z) + q4.w * (k1.y + pk.w);
        part += __shfl_xor_sync(0xffffffffu, part, 1);
        part += __shfl_xor_sync(0xffffffffu, part, 2);
        s[j] = part;
    }

    float mx = fmaxf(fmaxf(s[0], s[1]), fmaxf(s[2], s[3]));
    float e0 = __expf(s[0] - mx), e1 = __expf(s[1] - mx);
    float e2 = __expf(s[2] - mx), e3 = __expf(s[3] - mx);
    float inv = 1.0f / (e0 + e1 + e2 + e3);
    float a0 = e0 * inv, a1 = e1 * inv, a2 = e2 * inv, a3 = e3 * inv;

    sout[c0 + 0][w] = a0 * v4[0].x + a1 * v4[1].x + a2 * v4[2].x + a3 * v4[3].x;
    sout[c0 + 1][w] = a0 * v4[0].y + a1 * v4[1].y + a2 * v4[2].y + a3 * v4[3].y;
    sout[c0 + 2][w] = a0 * v4[0].z + a1 * v4[1].z + a2 * v4[2].z + a3 * v4[3].z;
    sout[c0 + 3][w] = a0 * v4[0].w + a1 * v4[1].w + a2 * v4[2].w + a3 * v4[3].w;
    __syncthreads();

    int p0 = blockIdx.x * 16;
    int n0 = p0 / HW;
    int hw0 = p0 - n0 * HW;
    int ch = tid >> 2;
    int px = (tid & 3) * 4;
    float4 v = make_float4(sout[ch][px], sout[ch][px + 1], sout[ch][px + 2], sout[ch][px + 3]);
    *(float4*)&out[(size_t)n0 * DIM * HW + (size_t)ch * HW + hw0 + px] = v;
}

// ---------------------------------------------------------------------------
extern "C" void kernel_launch(void* const* d_in, const int* in_sizes, int n_in,
                              void* d_out, int out_size) {
    const float* y      = (const float*)d_in[0];
    const float* x      = (const float*)d_in[1];
    const float* conv_w = (const float*)d_in[2];
    const float* conv_b = (const float*)d_in[3];
    const float* q_w    = (const float*)d_in[4];
    const float* q_b    = (const float*)d_in[5];
    const float* k_w    = (const float*)d_in[6];
    const float* k_b    = (const float*)d_in[7];
    const float* v_w    = (const float*)d_in[8];
    const float* v_b    = (const float*)d_in[9];
    float* out = (float*)d_out;

    static int smem_set = 0;
    const int GEMM_SMEM = 14336 + 14336 + 34816 + 512;  // 64000
    if (!smem_set) {
        cudaFuncSetAttribute(gemm_kernel,
                             cudaFuncAttributeMaxDynamicSharedMemorySize, GEMM_SMEM);
        smem_set = 1;
    }

    wtpb_kernel<<<7, 128>>>(q_w, q_b, k_w, k_b, v_w, v_b);

    dim3 cgrid(W / 32, H / 8, N_IMG * 4);
    dim3 cblk(32, 8);
    conv_slab_kernel<<<cgrid, cblk>>>(y, x, conv_w);
    finalize_kernel<<<NHW / 256, 256>>>(conv_b);

    dim3 ggrid(NHW / 128, 2);
    gemm_kernel<<<ggrid, 256, GEMM_SMEM>>>(y, x);

    attn_kernel<<<NHW / 16, 512>>>(out);
}